// round 1
// baseline (speedup 1.0000x reference)
#include <cuda_runtime.h>
#include <math.h>

#define Hdim 512
#define SHdim 120
#define Bdim 1024
#define Sdim 64
#define H3 1536
#define H4 2048
#define Mrows (Bdim*Sdim)   // 65536

// Scratch (device globals: allocation-free rule)
__device__ float g_G[Sdim*Bdim];                       // gate, transposed [s][b]
__device__ float g_xg[(size_t)Sdim*Bdim*H3];           // xg_all, layout [s][b][3H]
__device__ float g_h[2][Bdim*Hdim];                    // GRU hidden ping-pong

__device__ __forceinline__ float sigmoidf_(float x) { return 1.0f / (1.0f + expf(-x)); }

// ---------------------------------------------------------------------------
// init h0 = 0
// ---------------------------------------------------------------------------
__global__ void zero_h_kernel() {
    int i = blockIdx.x * blockDim.x + threadIdx.x;
    if (i < Bdim * Hdim) g_h[0][i] = 0.0f;
}

// ---------------------------------------------------------------------------
// Kernel 1: G[s][b] = sigmoid(fc2(tanh(fc1(feat))))
// feat(m,k): m in [0,65536), k in [0,2048). part = k>>9, base = k&511.
//   part0: C*Q   part1: C*prev_M   part2: |C-Q|   part3: |C-prev_M|
// GEMM tile: 64 rows x 128 cols (N=120 masked), K-chunk 32.
// ---------------------------------------------------------------------------
__global__ __launch_bounds__(256) void kernel_G(
    const float* __restrict__ C, const float* __restrict__ Q,
    const float* __restrict__ PM,
    const float* __restrict__ fc1w, const float* __restrict__ fc1b,
    const float* __restrict__ fc2w, const float* __restrict__ fc2b)
{
    __shared__ float As[32][68];    // [kk][m]
    __shared__ float Bs[32][132];   // [kk][n]

    const int tid = threadIdx.x;
    const int tn = tid & 15;        // 16 -> n = tn*8 .. +8
    const int tm = tid >> 4;        // 16 -> m = tm*4 .. +4
    const int m0 = blockIdx.x * 64;

    float acc[4][8];
    #pragma unroll
    for (int i = 0; i < 4; i++)
        #pragma unroll
        for (int j = 0; j < 8; j++) acc[i][j] = 0.0f;

    for (int k0 = 0; k0 < H4; k0 += 32) {
        const int part  = k0 >> 9;
        const int base0 = k0 & 511;

        // load A (feat) tile: 64 x 32 = 512 float4
        #pragma unroll
        for (int q = tid; q < 512; q += 256) {
            const int m  = q >> 3;
            const int kc = q & 7;
            const int mg = m0 + m;
            const float4 c4 = *(const float4*)(C + mg * Hdim + base0 + kc * 4);
            const int vrow  = (mg >> 6) * Hdim + base0 + kc * 4;
            float4 o4;
            if (part == 0) {
                const float4 v4 = *(const float4*)(Q + vrow);
                o4.x = c4.x * v4.x; o4.y = c4.y * v4.y; o4.z = c4.z * v4.z; o4.w = c4.w * v4.w;
            } else if (part == 1) {
                const float4 v4 = *(const float4*)(PM + vrow);
                o4.x = c4.x * v4.x; o4.y = c4.y * v4.y; o4.z = c4.z * v4.z; o4.w = c4.w * v4.w;
            } else if (part == 2) {
                const float4 v4 = *(const float4*)(Q + vrow);
                o4.x = fabsf(c4.x - v4.x); o4.y = fabsf(c4.y - v4.y);
                o4.z = fabsf(c4.z - v4.z); o4.w = fabsf(c4.w - v4.w);
            } else {
                const float4 v4 = *(const float4*)(PM + vrow);
                o4.x = fabsf(c4.x - v4.x); o4.y = fabsf(c4.y - v4.y);
                o4.z = fabsf(c4.z - v4.z); o4.w = fabsf(c4.w - v4.w);
            }
            As[kc * 4 + 0][m] = o4.x; As[kc * 4 + 1][m] = o4.y;
            As[kc * 4 + 2][m] = o4.z; As[kc * 4 + 3][m] = o4.w;
        }
        // load B tile: 128 x 32 = 1024 float4 (n >= 120 -> 0)
        #pragma unroll
        for (int q = tid; q < 1024; q += 256) {
            const int n  = q >> 3;
            const int kc = q & 7;
            float4 w4 = make_float4(0.f, 0.f, 0.f, 0.f);
            if (n < SHdim) w4 = *(const float4*)(fc1w + n * H4 + k0 + kc * 4);
            Bs[kc * 4 + 0][n] = w4.x; Bs[kc * 4 + 1][n] = w4.y;
            Bs[kc * 4 + 2][n] = w4.z; Bs[kc * 4 + 3][n] = w4.w;
        }
        __syncthreads();

        #pragma unroll 8
        for (int kk = 0; kk < 32; kk++) {
            float a[4], b[8];
            #pragma unroll
            for (int i = 0; i < 4; i++) a[i] = As[kk][tm * 4 + i];
            #pragma unroll
            for (int j = 0; j < 8; j++) b[j] = Bs[kk][tn * 8 + j];
            #pragma unroll
            for (int i = 0; i < 4; i++)
                #pragma unroll
                for (int j = 0; j < 8; j++) acc[i][j] += a[i] * b[j];
        }
        __syncthreads();
    }

    // epilogue: tanh + fc2 dot (reduce over the 16 tn-threads) + sigmoid
    const float fc2b0 = fc2b[0];
    #pragma unroll
    for (int i = 0; i < 4; i++) {
        float partial = 0.0f;
        #pragma unroll
        for (int j = 0; j < 8; j++) {
            const int n = tn * 8 + j;
            if (n < SHdim) partial += fc2w[n] * tanhf(acc[i][j] + fc1b[n]);
        }
        #pragma unroll
        for (int o = 8; o; o >>= 1)
            partial += __shfl_xor_sync(0xffffffffu, partial, o);
        if (tn == 0) {
            const int m = m0 + tm * 4 + i;            // m = b*64 + s
            g_G[(m & 63) * Bdim + (m >> 6)] = sigmoidf_(partial + fc2b0);
        }
    }
}

// ---------------------------------------------------------------------------
// Kernel 2: xg_all[s][b][n] = sum_k C[b,s,k] * W_ih[n,k] + b_ih[n]
// M=65536, N=1536, K=512. Tiles 128 x 64, K-chunk 32.
// ---------------------------------------------------------------------------
__global__ __launch_bounds__(256) void kernel_xg(
    const float* __restrict__ C, const float* __restrict__ Wih,
    const float* __restrict__ bih)
{
    __shared__ float As[32][132];   // [kk][m] (128 + pad)
    __shared__ float Bs[32][68];    // [kk][n] (64 + pad)

    const int tid = threadIdx.x;
    const int tn = tid & 15;        // 16 -> n = tn*4
    const int tm = tid >> 4;        // 16 -> m = tm*8
    const int m0 = blockIdx.x * 128;
    const int n0 = blockIdx.y * 64;

    float acc[8][4];
    #pragma unroll
    for (int i = 0; i < 8; i++)
        #pragma unroll
        for (int j = 0; j < 4; j++) acc[i][j] = 0.0f;

    for (int k0 = 0; k0 < Hdim; k0 += 32) {
        #pragma unroll
        for (int q = tid; q < 1024; q += 256) {      // 128x32 floats
            const int m  = q >> 3;
            const int kc = q & 7;
            const float4 c4 = *(const float4*)(C + (m0 + m) * Hdim + k0 + kc * 4);
            As[kc * 4 + 0][m] = c4.x; As[kc * 4 + 1][m] = c4.y;
            As[kc * 4 + 2][m] = c4.z; As[kc * 4 + 3][m] = c4.w;
        }
        #pragma unroll
        for (int q = tid; q < 512; q += 256) {       // 64x32 floats
            const int n  = q >> 3;
            const int kc = q & 7;
            const float4 w4 = *(const float4*)(Wih + (n0 + n) * Hdim + k0 + kc * 4);
            Bs[kc * 4 + 0][n] = w4.x; Bs[kc * 4 + 1][n] = w4.y;
            Bs[kc * 4 + 2][n] = w4.z; Bs[kc * 4 + 3][n] = w4.w;
        }
        __syncthreads();

        #pragma unroll 8
        for (int kk = 0; kk < 32; kk++) {
            float a[8], b[4];
            #pragma unroll
            for (int i = 0; i < 8; i++) a[i] = As[kk][tm * 8 + i];
            #pragma unroll
            for (int j = 0; j < 4; j++) b[j] = Bs[kk][tn * 4 + j];
            #pragma unroll
            for (int i = 0; i < 8; i++)
                #pragma unroll
                for (int j = 0; j < 4; j++) acc[i][j] += a[i] * b[j];
        }
        __syncthreads();
    }

    // write out: layout [s][b][3H] with bias
    const int ng = n0 + tn * 4;
    const float4 bi = *(const float4*)(bih + ng);
    #pragma unroll
    for (int i = 0; i < 8; i++) {
        const int m = m0 + tm * 8 + i;               // m = b*64 + s
        const size_t ob = ((size_t)(m & 63) * Bdim + (m >> 6)) * H3;
        float4 o4;
        o4.x = acc[i][0] + bi.x; o4.y = acc[i][1] + bi.y;
        o4.z = acc[i][2] + bi.z; o4.w = acc[i][3] + bi.w;
        *(float4*)(g_xg + ob + ng) = o4;
    }
}

// ---------------------------------------------------------------------------
// Kernel 3: one GRU step (fused hg-GEMM for r/z/n + gates).
// hg = h @ W_hh^T + b_hh ; tile 64(batch) x 64(j), 3 gate accumulators.
// ---------------------------------------------------------------------------
__global__ __launch_bounds__(256) void kernel_gru(
    const float* __restrict__ Whh, const float* __restrict__ bhh,
    int s, int parity, float* __restrict__ out_override)
{
    const float* __restrict__ h_in = g_h[parity];
    float* __restrict__ h_out = out_override ? out_override : g_h[parity ^ 1];

    __shared__ float As[32][68];      // [kk][b]
    __shared__ float Bs[3][32][68];   // [gate][kk][j]

    const int tid = threadIdx.x;
    const int tn = tid & 15;          // j = tn*4
    const int tm = tid >> 4;          // b = tm*4
    const int b0 = blockIdx.x * 64;
    const int j0 = blockIdx.y * 64;

    float acc[3][4][4];
    #pragma unroll
    for (int g = 0; g < 3; g++)
        #pragma unroll
        for (int i = 0; i < 4; i++)
            #pragma unroll
            for (int j = 0; j < 4; j++) acc[g][i][j] = 0.0f;

    for (int k0 = 0; k0 < Hdim; k0 += 32) {
        #pragma unroll
        for (int q = tid; q < 512; q += 256) {       // h tile 64x32
            const int m  = q >> 3;
            const int kc = q & 7;
            const float4 h4 = *(const float4*)(h_in + (b0 + m) * Hdim + k0 + kc * 4);
            As[kc * 4 + 0][m] = h4.x; As[kc * 4 + 1][m] = h4.y;
            As[kc * 4 + 2][m] = h4.z; As[kc * 4 + 3][m] = h4.w;
        }
        #pragma unroll
        for (int q = tid; q < 1536; q += 256) {      // 3 x 64 x 32 W tiles
            const int g  = q >> 9;
            const int r  = q & 511;
            const int j  = r >> 3;
            const int kc = r & 7;
            const float4 w4 = *(const float4*)(Whh + ((g << 9) + j0 + j) * Hdim + k0 + kc * 4);
            Bs[g][kc * 4 + 0][j] = w4.x; Bs[g][kc * 4 + 1][j] = w4.y;
            Bs[g][kc * 4 + 2][j] = w4.z; Bs[g][kc * 4 + 3][j] = w4.w;
        }
        __syncthreads();

        #pragma unroll 4
        for (int kk = 0; kk < 32; kk++) {
            float a[4];
            #pragma unroll
            for (int i = 0; i < 4; i++) a[i] = As[kk][tm * 4 + i];
            #pragma unroll
            for (int g = 0; g < 3; g++) {
                float b[4];
                #pragma unroll
                for (int j = 0; j < 4; j++) b[j] = Bs[g][kk][tn * 4 + j];
                #pragma unroll
                for (int i = 0; i < 4; i++)
                    #pragma unroll
                    for (int j = 0; j < 4; j++) acc[g][i][j] += a[i] * b[j];
            }
        }
        __syncthreads();
    }

    // gates + blend
    const float* __restrict__ xg_s = g_xg + (size_t)s * Bdim * H3;
    const float* __restrict__ G_s  = g_G + s * Bdim;
    #pragma unroll
    for (int i = 0; i < 4; i++) {
        const int bb = b0 + tm * 4 + i;
        const float gate = G_s[bb];
        const float* xrow = xg_s + (size_t)bb * H3;
        const float* hrow = h_in + bb * Hdim;
        #pragma unroll
        for (int j = 0; j < 4; j++) {
            const int jj = j0 + tn * 4 + j;
            const float hr = acc[0][i][j] + bhh[jj];
            const float hz = acc[1][i][j] + bhh[Hdim + jj];
            const float hn = acc[2][i][j] + bhh[2 * Hdim + jj];
            const float xr = xrow[jj];
            const float xz = xrow[Hdim + jj];
            const float xn = xrow[2 * Hdim + jj];
            const float hold = hrow[jj];
            const float r = sigmoidf_(xr + hr);
            const float z = sigmoidf_(xz + hz);
            const float n = tanhf(xn + r * hn);
            const float hgru = (1.0f - z) * n + z * hold;
            h_out[bb * Hdim + jj] = gate * hgru + (1.0f - gate) * hold;
        }
    }
}

// ---------------------------------------------------------------------------
extern "C" void kernel_launch(void* const* d_in, const int* in_sizes, int n_in,
                              void* d_out, int out_size)
{
    const float* C    = (const float*)d_in[0];
    const float* Q    = (const float*)d_in[1];
    const float* PM   = (const float*)d_in[2];
    const float* fc1w = (const float*)d_in[3];
    const float* fc1b = (const float*)d_in[4];
    const float* fc2w = (const float*)d_in[5];
    const float* fc2b = (const float*)d_in[6];
    const float* Wih  = (const float*)d_in[7];
    const float* Whh  = (const float*)d_in[8];
    const float* bih  = (const float*)d_in[9];
    const float* bhh  = (const float*)d_in[10];
    float* out = (float*)d_out;

    zero_h_kernel<<<(Bdim * Hdim + 255) / 256, 256>>>();
    kernel_G<<<Mrows / 64, 256>>>(C, Q, PM, fc1w, fc1b, fc2w, fc2b);
    kernel_xg<<<dim3(Mrows / 128, H3 / 64), 256>>>(C, Wih, bih);
    for (int s = 0; s < Sdim; s++) {
        kernel_gru<<<dim3(Bdim / 64, Hdim / 64), 256>>>(
            Whh, bhh, s, s & 1, (s == Sdim - 1) ? out : nullptr);
    }
}

// round 2
// speedup vs baseline: 1.0006x; 1.0006x over previous
#include <cuda_runtime.h>
#include <math.h>

#define Hdim 512
#define SHdim 120
#define Bdim 1024
#define Sdim 64
#define H3 1536
#define H4 2048
#define Mrows (Bdim*Sdim)   // 65536

// Scratch (device globals: allocation-free rule)
__device__ float g_G[Sdim*Bdim];                       // gate, transposed [s][b]
__device__ float g_xg[(size_t)Sdim*Bdim*H3];           // xg_all, layout [s][b][3H]
__device__ float g_h[2][Bdim*Hdim];                    // GRU hidden ping-pong

__device__ __forceinline__ float sigmoidf_(float x) { return 1.0f / (1.0f + expf(-x)); }

// ---------------------------------------------------------------------------
// init h0 = 0
// ---------------------------------------------------------------------------
__global__ void zero_h_kernel() {
    int i = blockIdx.x * blockDim.x + threadIdx.x;
    if (i < Bdim * Hdim) g_h[0][i] = 0.0f;
}

// ---------------------------------------------------------------------------
// Kernel 1: G[s][b] = sigmoid(fc2(tanh(fc1(feat))))
// feat(m,k): m in [0,65536), k in [0,2048). part = k>>9, base = k&511.
//   part0: C*Q   part1: C*prev_M   part2: |C-Q|   part3: |C-prev_M|
// GEMM tile: 64 rows x 128 cols (N=120 masked), K-chunk 32.
// ---------------------------------------------------------------------------
__global__ __launch_bounds__(256) void kernel_G(
    const float* __restrict__ C, const float* __restrict__ Q,
    const float* __restrict__ PM,
    const float* __restrict__ fc1w, const float* __restrict__ fc1b,
    const float* __restrict__ fc2w, const float* __restrict__ fc2b)
{
    __shared__ float As[32][68];    // [kk][m]
    __shared__ float Bs[32][132];   // [kk][n]

    const int tid = threadIdx.x;
    const int tn = tid & 15;        // 16 -> n = tn*8 .. +8
    const int tm = tid >> 4;        // 16 -> m = tm*4 .. +4
    const int m0 = blockIdx.x * 64;

    float acc[4][8];
    #pragma unroll
    for (int i = 0; i < 4; i++)
        #pragma unroll
        for (int j = 0; j < 8; j++) acc[i][j] = 0.0f;

    for (int k0 = 0; k0 < H4; k0 += 32) {
        const int part  = k0 >> 9;
        const int base0 = k0 & 511;

        // load A (feat) tile: 64 x 32 = 512 float4
        #pragma unroll
        for (int q = tid; q < 512; q += 256) {
            const int m  = q >> 3;
            const int kc = q & 7;
            const int mg = m0 + m;
            const float4 c4 = *(const float4*)(C + mg * Hdim + base0 + kc * 4);
            const int vrow  = (mg >> 6) * Hdim + base0 + kc * 4;
            float4 o4;
            if (part == 0) {
                const float4 v4 = *(const float4*)(Q + vrow);
                o4.x = c4.x * v4.x; o4.y = c4.y * v4.y; o4.z = c4.z * v4.z; o4.w = c4.w * v4.w;
            } else if (part == 1) {
                const float4 v4 = *(const float4*)(PM + vrow);
                o4.x = c4.x * v4.x; o4.y = c4.y * v4.y; o4.z = c4.z * v4.z; o4.w = c4.w * v4.w;
            } else if (part == 2) {
                const float4 v4 = *(const float4*)(Q + vrow);
                o4.x = fabsf(c4.x - v4.x); o4.y = fabsf(c4.y - v4.y);
                o4.z = fabsf(c4.z - v4.z); o4.w = fabsf(c4.w - v4.w);
            } else {
                const float4 v4 = *(const float4*)(PM + vrow);
                o4.x = fabsf(c4.x - v4.x); o4.y = fabsf(c4.y - v4.y);
                o4.z = fabsf(c4.z - v4.z); o4.w = fabsf(c4.w - v4.w);
            }
            As[kc * 4 + 0][m] = o4.x; As[kc * 4 + 1][m] = o4.y;
            As[kc * 4 + 2][m] = o4.z; As[kc * 4 + 3][m] = o4.w;
        }
        // load B tile: 128 x 32 = 1024 float4 (n >= 120 -> 0)
        #pragma unroll
        for (int q = tid; q < 1024; q += 256) {
            const int n  = q >> 3;
            const int kc = q & 7;
            float4 w4 = make_float4(0.f, 0.f, 0.f, 0.f);
            if (n < SHdim) w4 = *(const float4*)(fc1w + n * H4 + k0 + kc * 4);
            Bs[kc * 4 + 0][n] = w4.x; Bs[kc * 4 + 1][n] = w4.y;
            Bs[kc * 4 + 2][n] = w4.z; Bs[kc * 4 + 3][n] = w4.w;
        }
        __syncthreads();

        #pragma unroll 8
        for (int kk = 0; kk < 32; kk++) {
            float a[4], b[8];
            #pragma unroll
            for (int i = 0; i < 4; i++) a[i] = As[kk][tm * 4 + i];
            #pragma unroll
            for (int j = 0; j < 8; j++) b[j] = Bs[kk][tn * 8 + j];
            #pragma unroll
            for (int i = 0; i < 4; i++)
                #pragma unroll
                for (int j = 0; j < 8; j++) acc[i][j] += a[i] * b[j];
        }
        __syncthreads();
    }

    // epilogue: tanh + fc2 dot (reduce over the 16 tn-threads) + sigmoid
    const float fc2b0 = fc2b[0];
    #pragma unroll
    for (int i = 0; i < 4; i++) {
        float partial = 0.0f;
        #pragma unroll
        for (int j = 0; j < 8; j++) {
            const int n = tn * 8 + j;
            if (n < SHdim) partial += fc2w[n] * tanhf(acc[i][j] + fc1b[n]);
        }
        #pragma unroll
        for (int o = 8; o; o >>= 1)
            partial += __shfl_xor_sync(0xffffffffu, partial, o);
        if (tn == 0) {
            const int m = m0 + tm * 4 + i;            // m = b*64 + s
            g_G[(m & 63) * Bdim + (m >> 6)] = sigmoidf_(partial + fc2b0);
        }
    }
}

// ---------------------------------------------------------------------------
// Kernel 2: xg_all[s][b][n] = sum_k C[b,s,k] * W_ih[n,k] + b_ih[n]
// M=65536, N=1536, K=512. Tiles 128 x 64, K-chunk 32.
// ---------------------------------------------------------------------------
__global__ __launch_bounds__(256) void kernel_xg(
    const float* __restrict__ C, const float* __restrict__ Wih,
    const float* __restrict__ bih)
{
    __shared__ float As[32][132];   // [kk][m] (128 + pad)
    __shared__ float Bs[32][68];    // [kk][n] (64 + pad)

    const int tid = threadIdx.x;
    const int tn = tid & 15;        // 16 -> n = tn*4
    const int tm = tid >> 4;        // 16 -> m = tm*8
    const int m0 = blockIdx.x * 128;
    const int n0 = blockIdx.y * 64;

    float acc[8][4];
    #pragma unroll
    for (int i = 0; i < 8; i++)
        #pragma unroll
        for (int j = 0; j < 4; j++) acc[i][j] = 0.0f;

    for (int k0 = 0; k0 < Hdim; k0 += 32) {
        #pragma unroll
        for (int q = tid; q < 1024; q += 256) {      // 128x32 floats
            const int m  = q >> 3;
            const int kc = q & 7;
            const float4 c4 = *(const float4*)(C + (m0 + m) * Hdim + k0 + kc * 4);
            As[kc * 4 + 0][m] = c4.x; As[kc * 4 + 1][m] = c4.y;
            As[kc * 4 + 2][m] = c4.z; As[kc * 4 + 3][m] = c4.w;
        }
        #pragma unroll
        for (int q = tid; q < 512; q += 256) {       // 64x32 floats
            const int n  = q >> 3;
            const int kc = q & 7;
            const float4 w4 = *(const float4*)(Wih + (n0 + n) * Hdim + k0 + kc * 4);
            Bs[kc * 4 + 0][n] = w4.x; Bs[kc * 4 + 1][n] = w4.y;
            Bs[kc * 4 + 2][n] = w4.z; Bs[kc * 4 + 3][n] = w4.w;
        }
        __syncthreads();

        #pragma unroll 8
        for (int kk = 0; kk < 32; kk++) {
            float a[8], b[4];
            #pragma unroll
            for (int i = 0; i < 8; i++) a[i] = As[kk][tm * 8 + i];
            #pragma unroll
            for (int j = 0; j < 4; j++) b[j] = Bs[kk][tn * 4 + j];
            #pragma unroll
            for (int i = 0; i < 8; i++)
                #pragma unroll
                for (int j = 0; j < 4; j++) acc[i][j] += a[i] * b[j];
        }
        __syncthreads();
    }

    // write out: layout [s][b][3H] with bias
    const int ng = n0 + tn * 4;
    const float4 bi = *(const float4*)(bih + ng);
    #pragma unroll
    for (int i = 0; i < 8; i++) {
        const int m = m0 + tm * 8 + i;               // m = b*64 + s
        const size_t ob = ((size_t)(m & 63) * Bdim + (m >> 6)) * H3;
        float4 o4;
        o4.x = acc[i][0] + bi.x; o4.y = acc[i][1] + bi.y;
        o4.z = acc[i][2] + bi.z; o4.w = acc[i][3] + bi.w;
        *(float4*)(g_xg + ob + ng) = o4;
    }
}

// ---------------------------------------------------------------------------
// Kernel 3: one GRU step (fused hg-GEMM for r/z/n + gates).
// hg = h @ W_hh^T + b_hh ; tile 64(batch) x 64(j), 3 gate accumulators.
// ---------------------------------------------------------------------------
__global__ __launch_bounds__(256) void kernel_gru(
    const float* __restrict__ Whh, const float* __restrict__ bhh,
    int s, int parity, float* __restrict__ out_override)
{
    const float* __restrict__ h_in = g_h[parity];
    float* __restrict__ h_out = out_override ? out_override : g_h[parity ^ 1];

    __shared__ float As[32][68];      // [kk][b]
    __shared__ float Bs[3][32][68];   // [gate][kk][j]

    const int tid = threadIdx.x;
    const int tn = tid & 15;          // j = tn*4
    const int tm = tid >> 4;          // b = tm*4
    const int b0 = blockIdx.x * 64;
    const int j0 = blockIdx.y * 64;

    float acc[3][4][4];
    #pragma unroll
    for (int g = 0; g < 3; g++)
        #pragma unroll
        for (int i = 0; i < 4; i++)
            #pragma unroll
            for (int j = 0; j < 4; j++) acc[g][i][j] = 0.0f;

    for (int k0 = 0; k0 < Hdim; k0 += 32) {
        #pragma unroll
        for (int q = tid; q < 512; q += 256) {       // h tile 64x32
            const int m  = q >> 3;
            const int kc = q & 7;
            const float4 h4 = *(const float4*)(h_in + (b0 + m) * Hdim + k0 + kc * 4);
            As[kc * 4 + 0][m] = h4.x; As[kc * 4 + 1][m] = h4.y;
            As[kc * 4 + 2][m] = h4.z; As[kc * 4 + 3][m] = h4.w;
        }
        #pragma unroll
        for (int q = tid; q < 1536; q += 256) {      // 3 x 64 x 32 W tiles
            const int g  = q >> 9;
            const int r  = q & 511;
            const int j  = r >> 3;
            const int kc = r & 7;
            const float4 w4 = *(const float4*)(Whh + ((g << 9) + j0 + j) * Hdim + k0 + kc * 4);
            Bs[g][kc * 4 + 0][j] = w4.x; Bs[g][kc * 4 + 1][j] = w4.y;
            Bs[g][kc * 4 + 2][j] = w4.z; Bs[g][kc * 4 + 3][j] = w4.w;
        }
        __syncthreads();

        #pragma unroll 4
        for (int kk = 0; kk < 32; kk++) {
            float a[4];
            #pragma unroll
            for (int i = 0; i < 4; i++) a[i] = As[kk][tm * 4 + i];
            #pragma unroll
            for (int g = 0; g < 3; g++) {
                float b[4];
                #pragma unroll
                for (int j = 0; j < 4; j++) b[j] = Bs[g][kk][tn * 4 + j];
                #pragma unroll
                for (int i = 0; i < 4; i++)
                    #pragma unroll
                    for (int j = 0; j < 4; j++) acc[g][i][j] += a[i] * b[j];
            }
        }
        __syncthreads();
    }

    // gates + blend
    const float* __restrict__ xg_s = g_xg + (size_t)s * Bdim * H3;
    const float* __restrict__ G_s  = g_G + s * Bdim;
    #pragma unroll
    for (int i = 0; i < 4; i++) {
        const int bb = b0 + tm * 4 + i;
        const float gate = G_s[bb];
        const float* xrow = xg_s + (size_t)bb * H3;
        const float* hrow = h_in + bb * Hdim;
        #pragma unroll
        for (int j = 0; j < 4; j++) {
            const int jj = j0 + tn * 4 + j;
            const float hr = acc[0][i][j] + bhh[jj];
            const float hz = acc[1][i][j] + bhh[Hdim + jj];
            const float hn = acc[2][i][j] + bhh[2 * Hdim + jj];
            const float xr = xrow[jj];
            const float xz = xrow[Hdim + jj];
            const float xn = xrow[2 * Hdim + jj];
            const float hold = hrow[jj];
            const float r = sigmoidf_(xr + hr);
            const float z = sigmoidf_(xz + hz);
            const float n = tanhf(xn + r * hn);
            const float hgru = (1.0f - z) * n + z * hold;
            h_out[bb * Hdim + jj] = gate * hgru + (1.0f - gate) * hold;
        }
    }
}

// ---------------------------------------------------------------------------
extern "C" void kernel_launch(void* const* d_in, const int* in_sizes, int n_in,
                              void* d_out, int out_size)
{
    const float* C    = (const float*)d_in[0];
    const float* Q    = (const float*)d_in[1];
    const float* PM   = (const float*)d_in[2];
    const float* fc1w = (const float*)d_in[3];
    const float* fc1b = (const float*)d_in[4];
    const float* fc2w = (const float*)d_in[5];
    const float* fc2b = (const float*)d_in[6];
    const float* Wih  = (const float*)d_in[7];
    const float* Whh  = (const float*)d_in[8];
    const float* bih  = (const float*)d_in[9];
    const float* bhh  = (const float*)d_in[10];
    float* out = (float*)d_out;

    zero_h_kernel<<<(Bdim * Hdim + 255) / 256, 256>>>();
    kernel_G<<<Mrows / 64, 256>>>(C, Q, PM, fc1w, fc1b, fc2w, fc2b);
    kernel_xg<<<dim3(Mrows / 128, H3 / 64), 256>>>(C, Wih, bih);
    for (int s = 0; s < Sdim; s++) {
        kernel_gru<<<dim3(Bdim / 64, Hdim / 64), 256>>>(
            Whh, bhh, s, s & 1, (s == Sdim - 1) ? out : nullptr);
    }
}

// round 4
// speedup vs baseline: 1.1746x; 1.1739x over previous
#include <cuda_runtime.h>
#include <cuda_bf16.h>
#include <math.h>
#include <stdint.h>

#define Hdim 512
#define SHdim 120
#define Bdim 1024
#define Sdim 64
#define H3 1536
#define H4 2048
#define Mrows (Bdim*Sdim)

// ----------------------------- device scratch ------------------------------
__device__ float g_G[Sdim*Bdim];
__device__ float g_xg[(size_t)Sdim*Bdim*H3];
__device__ float g_hf[2][Bdim*Hdim];
__device__ __nv_bfloat16 g_hhi[2][Bdim*Hdim];
__device__ __nv_bfloat16 g_hlo[2][Bdim*Hdim];
__device__ __nv_bfloat16 g_Chi[(size_t)Mrows*Hdim];
__device__ __nv_bfloat16 g_Clo[(size_t)Mrows*Hdim];
__device__ __nv_bfloat16 g_Wihhi[H3*Hdim];
__device__ __nv_bfloat16 g_Wihlo[H3*Hdim];
__device__ __nv_bfloat16 g_Whhhi[H3*Hdim];
__device__ __nv_bfloat16 g_Whhlo[H3*Hdim];

__device__ __forceinline__ float sigmoidf_(float x){ return 1.0f/(1.0f+expf(-x)); }

// ----------------------------- mma helpers ---------------------------------
__device__ __forceinline__ uint32_t smem_u32(const void* p){
    uint32_t a;
    asm("{ .reg .u64 t; cvta.to.shared.u64 t, %1; cvt.u32.u64 %0, t; }" : "=r"(a) : "l"(p));
    return a;
}
__device__ __forceinline__ void mma16816(float* c, uint32_t a0, uint32_t a1,
                                         uint32_t a2, uint32_t a3,
                                         uint32_t b0, uint32_t b1){
    asm volatile(
        "mma.sync.aligned.m16n8k16.row.col.f32.bf16.bf16.f32 "
        "{%0,%1,%2,%3},{%4,%5,%6,%7},{%8,%9},{%0,%1,%2,%3};"
        : "+f"(c[0]), "+f"(c[1]), "+f"(c[2]), "+f"(c[3])
        : "r"(a0), "r"(a1), "r"(a2), "r"(a3), "r"(b0), "r"(b1));
}
#define LDSM4(r0,r1,r2,r3, addr) \
    asm volatile("ldmatrix.sync.aligned.m8n8.x4.shared.b16 {%0,%1,%2,%3}, [%4];" \
        : "=r"(r0), "=r"(r1), "=r"(r2), "=r"(r3) : "r"(addr))
#define STS16(dst, v) asm volatile("st.shared.v4.b32 [%0],{%1,%2,%3,%4};" \
        :: "r"(dst), "r"((v).x), "r"((v).y), "r"((v).z), "r"((v).w))

#define LD 80   // padded smem row stride in bytes for a 32-bf16 (64B) k-chunk row

// ----------------------------- init / split --------------------------------
__global__ void zero3_kernel(){
    int i = blockIdx.x * blockDim.x + threadIdx.x;
    if (i < Bdim * Hdim) {
        g_hf[0][i] = 0.0f;
        g_hhi[0][i] = __float2bfloat16_rn(0.0f);
        g_hlo[0][i] = __float2bfloat16_rn(0.0f);
    }
}
__device__ __forceinline__ void split4(float4 v, uint2* hi, uint2* lo){
    __nv_bfloat162 h0(__float2bfloat16_rn(v.x), __float2bfloat16_rn(v.y));
    __nv_bfloat162 h1(__float2bfloat16_rn(v.z), __float2bfloat16_rn(v.w));
    __nv_bfloat162 l0(__float2bfloat16_rn(v.x - __bfloat162float(h0.x)),
                      __float2bfloat16_rn(v.y - __bfloat162float(h0.y)));
    __nv_bfloat162 l1(__float2bfloat16_rn(v.z - __bfloat162float(h1.x)),
                      __float2bfloat16_rn(v.w - __bfloat162float(h1.y)));
    hi->x = *(uint32_t*)&h0; hi->y = *(uint32_t*)&h1;
    lo->x = *(uint32_t*)&l0; lo->y = *(uint32_t*)&l1;
}
__global__ void split_C_kernel(const float* __restrict__ src){
    size_t i = (size_t)blockIdx.x * blockDim.x + threadIdx.x;   // 8388608 float4
    uint2 h, l;
    split4(((const float4*)src)[i], &h, &l);
    ((uint2*)g_Chi)[i] = h;
    ((uint2*)g_Clo)[i] = l;
}
__global__ void split_W_kernel(const float* __restrict__ wih, const float* __restrict__ whh){
    int i = blockIdx.x * blockDim.x + threadIdx.x;              // 2*196608
    const int nW = H3 * Hdim / 4;
    uint2 h, l;
    if (i < nW) {
        split4(((const float4*)wih)[i], &h, &l);
        ((uint2*)g_Wihhi)[i] = h; ((uint2*)g_Wihlo)[i] = l;
    } else {
        int j = i - nW;
        split4(((const float4*)whh)[j], &h, &l);
        ((uint2*)g_Whhhi)[j] = h; ((uint2*)g_Whhlo)[j] = l;
    }
}

// ---------------------------------------------------------------------------
// Gate network (fp32, validated in R1)
// ---------------------------------------------------------------------------
__global__ __launch_bounds__(256) void kernel_G(
    const float* __restrict__ C, const float* __restrict__ Q,
    const float* __restrict__ PM,
    const float* __restrict__ fc1w, const float* __restrict__ fc1b,
    const float* __restrict__ fc2w, const float* __restrict__ fc2b)
{
    __shared__ float As[32][68];
    __shared__ float Bs[32][132];
    const int tid = threadIdx.x;
    const int tn = tid & 15;
    const int tm = tid >> 4;
    const int m0 = blockIdx.x * 64;
    float acc[4][8];
    #pragma unroll
    for (int i = 0; i < 4; i++)
        #pragma unroll
        for (int j = 0; j < 8; j++) acc[i][j] = 0.0f;

    for (int k0 = 0; k0 < H4; k0 += 32) {
        const int part = k0 >> 9;
        const int base0 = k0 & 511;
        #pragma unroll
        for (int q = tid; q < 512; q += 256) {
            const int m = q >> 3, kc = q & 7, mg = m0 + m;
            const float4 c4 = *(const float4*)(C + mg * Hdim + base0 + kc * 4);
            const int vrow = (mg >> 6) * Hdim + base0 + kc * 4;
            const float4 v4 = (part == 0 || part == 2) ? *(const float4*)(Q + vrow)
                                                       : *(const float4*)(PM + vrow);
            float4 o4;
            if (part < 2) { o4.x = c4.x*v4.x; o4.y = c4.y*v4.y; o4.z = c4.z*v4.z; o4.w = c4.w*v4.w; }
            else { o4.x = fabsf(c4.x-v4.x); o4.y = fabsf(c4.y-v4.y); o4.z = fabsf(c4.z-v4.z); o4.w = fabsf(c4.w-v4.w); }
            As[kc*4+0][m] = o4.x; As[kc*4+1][m] = o4.y; As[kc*4+2][m] = o4.z; As[kc*4+3][m] = o4.w;
        }
        #pragma unroll
        for (int q = tid; q < 1024; q += 256) {
            const int n = q >> 3, kc = q & 7;
            float4 w4 = make_float4(0.f,0.f,0.f,0.f);
            if (n < SHdim) w4 = *(const float4*)(fc1w + n * H4 + k0 + kc * 4);
            Bs[kc*4+0][n] = w4.x; Bs[kc*4+1][n] = w4.y; Bs[kc*4+2][n] = w4.z; Bs[kc*4+3][n] = w4.w;
        }
        __syncthreads();
        #pragma unroll 8
        for (int kk = 0; kk < 32; kk++) {
            float a[4], b[8];
            #pragma unroll
            for (int i = 0; i < 4; i++) a[i] = As[kk][tm*4+i];
            #pragma unroll
            for (int j = 0; j < 8; j++) b[j] = Bs[kk][tn*8+j];
            #pragma unroll
            for (int i = 0; i < 4; i++)
                #pragma unroll
                for (int j = 0; j < 8; j++) acc[i][j] += a[i] * b[j];
        }
        __syncthreads();
    }
    const float fc2b0 = fc2b[0];
    #pragma unroll
    for (int i = 0; i < 4; i++) {
        float partial = 0.0f;
        #pragma unroll
        for (int j = 0; j < 8; j++) {
            const int n = tn*8+j;
            if (n < SHdim) partial += fc2w[n] * tanhf(acc[i][j] + fc1b[n]);
        }
        #pragma unroll
        for (int o = 8; o; o >>= 1) partial += __shfl_xor_sync(0xffffffffu, partial, o);
        if (tn == 0) {
            const int m = m0 + tm*4 + i;
            g_G[(m & 63) * Bdim + (m >> 6)] = sigmoidf_(partial + fc2b0);
        }
    }
}

// ---------------------------------------------------------------------------
// xg = C @ Wih^T + b via split-bf16 HMMA. CTA 128(m) x 256(n), 512 threads.
// K: 3 terms (AhiBhi, AhiBlo, AloBhi) x 512 = 48 chunks of k32, double-buffered.
// ---------------------------------------------------------------------------
#define XA_SZ (128*LD)          // 10240
#define XB_SZ (256*LD)          // 20480
#define XBUF  (XA_SZ + XB_SZ)   // 30720

__device__ __forceinline__ void xg_load(uint32_t buf, int tid, int m0, int n0, int c){
    const __nv_bfloat16* __restrict__ Asrc = (c < 32) ? g_Chi : g_Clo;
    const __nv_bfloat16* __restrict__ Bsrc = (c >= 16 && c < 32) ? g_Wihlo : g_Wihhi;
    const int k0 = (c & 15) * 32;
    {   // A: 512 uint4, 512 threads
        const int u = tid & 3, r = tid >> 2;
        uint4 v = *(const uint4*)(Asrc + (size_t)(m0 + r) * Hdim + k0 + u * 8);
        STS16(buf + r * LD + u * 16, v);
    }
    #pragma unroll
    for (int i = 0; i < 2; i++) {   // B: 1024 uint4
        const int q = tid + i * 512;
        const int u = q & 3, r = q >> 2;
        uint4 v = *(const uint4*)(Bsrc + (size_t)(n0 + r) * Hdim + k0 + u * 8);
        STS16(buf + XA_SZ + r * LD + u * 16, v);
    }
}

__global__ __launch_bounds__(512, 1) void xg_mma(const float* __restrict__ bih)
{
    extern __shared__ __align__(16) char smx[];
    const uint32_t sb = smem_u32(smx);
    const int tid = threadIdx.x, lane = tid & 31, wid = tid >> 5;
    const int wm = wid >> 3, wn = wid & 7;     // warp: m 64, n 32
    const int m0 = blockIdx.x * 128, n0 = blockIdx.y * 256;

    float acc[4][4][4];
    #pragma unroll
    for (int a = 0; a < 4; a++)
        #pragma unroll
        for (int b = 0; b < 4; b++)
            #pragma unroll
            for (int d = 0; d < 4; d++) acc[a][b][d] = 0.0f;

    xg_load(sb, tid, m0, n0, 0);
    __syncthreads();

    const uint32_t a_lrow = (lane & 15) * LD + (lane >> 4) * 16;
    const uint32_t b_lrow = ((lane >> 4) * 8 + (lane & 7)) * LD + ((lane >> 3) & 1) * 16;

    for (int c = 0; c < 48; c++) {
        const uint32_t cur = sb + (c & 1) * XBUF;
        if (c + 1 < 48) xg_load(sb + ((c + 1) & 1) * XBUF, tid, m0, n0, c + 1);
        #pragma unroll
        for (int kk = 0; kk < 2; kk++) {
            uint32_t a[4][4];
            #pragma unroll
            for (int mf = 0; mf < 4; mf++) {
                LDSM4(a[mf][0], a[mf][1], a[mf][2], a[mf][3],
                      cur + (wm * 64 + mf * 16) * LD + kk * 32 + a_lrow);
            }
            #pragma unroll
            for (int nfp = 0; nfp < 2; nfp++) {
                uint32_t b0, b1, b2, b3;
                LDSM4(b0, b1, b2, b3,
                      cur + XA_SZ + (wn * 32 + nfp * 16) * LD + kk * 32 + b_lrow);
                #pragma unroll
                for (int mf = 0; mf < 4; mf++) {
                    mma16816(acc[mf][nfp*2],   a[mf][0], a[mf][1], a[mf][2], a[mf][3], b0, b1);
                    mma16816(acc[mf][nfp*2+1], a[mf][0], a[mf][1], a[mf][2], a[mf][3], b2, b3);
                }
            }
        }
        __syncthreads();
    }

    // epilogue: + bih, write to g_xg[s][b][n]  (m = b*64 + s)
    #pragma unroll
    for (int mf = 0; mf < 4; mf++) {
        #pragma unroll
        for (int half = 0; half < 2; half++) {
            const int m = m0 + wm * 64 + mf * 16 + (lane >> 2) + half * 8;
            const size_t ob = ((size_t)(m & 63) * Bdim + (m >> 6)) * H3;
            #pragma unroll
            for (int nf = 0; nf < 4; nf++) {
                const int jj = n0 + wn * 32 + nf * 8 + (lane & 3) * 2;
                float2 o;
                o.x = acc[mf][nf][half*2+0] + bih[jj];
                o.y = acc[mf][nf][half*2+1] + bih[jj+1];
                *(float2*)(g_xg + ob + jj) = o;
            }
        }
    }
}

// ---------------------------------------------------------------------------
// GRU step via split-bf16 HMMA. CTA 64(batch) x 64(j) x 3 gates, 256 threads.
// ---------------------------------------------------------------------------
#define GA_SZ (64*LD)            // 5120
#define GB_SZ (192*LD)           // 15360
#define GBUF  (GA_SZ + GB_SZ)    // 20480

__device__ __forceinline__ void gru_load(uint32_t buf, int tid, int b0, int j0, int c,
                                         const __nv_bfloat16* __restrict__ hhi,
                                         const __nv_bfloat16* __restrict__ hlo){
    const __nv_bfloat16* __restrict__ Asrc = (c < 32) ? hhi : hlo;
    const __nv_bfloat16* __restrict__ Bsrc = (c >= 16 && c < 32) ? g_Whhlo : g_Whhhi;
    const int k0 = (c & 15) * 32;
    {   // A: 256 uint4
        const int u = tid & 3, r = tid >> 2;
        uint4 v = *(const uint4*)(Asrc + (b0 + r) * Hdim + k0 + u * 8);
        STS16(buf + r * LD + u * 16, v);
    }
    #pragma unroll
    for (int i = 0; i < 3; i++) {   // B: 768 uint4 (3 gates x 64 rows)
        const int q = tid + i * 256;
        const int u = q & 3, r = q >> 2;
        const int n = ((r >> 6) << 9) + j0 + (r & 63);
        uint4 v = *(const uint4*)(Bsrc + n * Hdim + k0 + u * 8);
        STS16(buf + GA_SZ + r * LD + u * 16, v);
    }
}

__global__ __launch_bounds__(256, 2) void gru_mma(
    const float* __restrict__ bhh, int s, int par, float* __restrict__ outp)
{
    __shared__ __align__(16) char smg[2 * GBUF];
    const uint32_t sb = smem_u32(smg);
    const int tid = threadIdx.x, lane = tid & 31, wid = tid >> 5;
    const int wm = wid >> 1, wn = wid & 1;     // warp: m 16, n 32
    const int b0 = blockIdx.x * 64, j0 = blockIdx.y * 64;
    const __nv_bfloat16* __restrict__ hhi = g_hhi[par];
    const __nv_bfloat16* __restrict__ hlo = g_hlo[par];

    float acc[3][4][4];
    #pragma unroll
    for (int g = 0; g < 3; g++)
        #pragma unroll
        for (int b = 0; b < 4; b++)
            #pragma unroll
            for (int d = 0; d < 4; d++) acc[g][b][d] = 0.0f;

    gru_load(sb, tid, b0, j0, 0, hhi, hlo);
    __syncthreads();

    const uint32_t a_lrow = (wm * 16 + (lane & 15)) * LD + (lane >> 4) * 16;
    const uint32_t b_lrow = ((lane >> 4) * 8 + (lane & 7)) * LD + ((lane >> 3) & 1) * 16;

    for (int c = 0; c < 48; c++) {
        const uint32_t cur = sb + (c & 1) * GBUF;
        if (c + 1 < 48) gru_load(sb + ((c + 1) & 1) * GBUF, tid, b0, j0, c + 1, hhi, hlo);
        #pragma unroll
        for (int kk = 0; kk < 2; kk++) {
            uint32_t a0, a1, a2, a3;
            LDSM4(a0, a1, a2, a3, cur + kk * 32 + a_lrow);
            #pragma unroll
            for (int g = 0; g < 3; g++) {
                #pragma unroll
                for (int nfp = 0; nfp < 2; nfp++) {
                    uint32_t b0r, b1r, b2r, b3r;
                    LDSM4(b0r, b1r, b2r, b3r,
                          cur + GA_SZ + (g * 64 + wn * 32 + nfp * 16) * LD + kk * 32 + b_lrow);
                    mma16816(acc[g][nfp*2],   a0, a1, a2, a3, b0r, b1r);
                    mma16816(acc[g][nfp*2+1], a0, a1, a2, a3, b2r, b3r);
                }
            }
        }
        __syncthreads();
    }

    // epilogue: gates + blend, write h (fp32 + bf16 hi/lo) or final out
    const float* __restrict__ xg_s = g_xg + (size_t)s * Bdim * H3;
    float* __restrict__ hout = g_hf[par ^ 1];
    __nv_bfloat16* __restrict__ hhiN = g_hhi[par ^ 1];
    __nv_bfloat16* __restrict__ hloN = g_hlo[par ^ 1];

    #pragma unroll
    for (int half = 0; half < 2; half++) {
        const int bb = b0 + wm * 16 + (lane >> 2) + half * 8;
        const float gate = g_G[s * Bdim + bb];
        const float* __restrict__ xrow = xg_s + (size_t)bb * H3;
        const float* __restrict__ hrow = g_hf[par] + bb * Hdim;
        #pragma unroll
        for (int nf = 0; nf < 4; nf++) {
            #pragma unroll
            for (int cc = 0; cc < 2; cc++) {
                const int jj = j0 + wn * 32 + nf * 8 + (lane & 3) * 2 + cc;
                const int ai = half * 2 + cc;
                const float hr = acc[0][nf][ai] + bhh[jj];
                const float hz = acc[1][nf][ai] + bhh[Hdim + jj];
                const float hn = acc[2][nf][ai] + bhh[2 * Hdim + jj];
                const float r = sigmoidf_(xrow[jj] + hr);
                const float z = sigmoidf_(xrow[Hdim + jj] + hz);
                const float n = tanhf(xrow[2 * Hdim + jj] + r * hn);
                const float hold = hrow[jj];
                const float hnew = gate * ((1.0f - z) * n + z * hold) + (1.0f - gate) * hold;
                if (outp) {
                    outp[bb * Hdim + jj] = hnew;
                } else {
                    hout[bb * Hdim + jj] = hnew;
                    const __nv_bfloat16 hb = __float2bfloat16_rn(hnew);
                    hhiN[bb * Hdim + jj] = hb;
                    hloN[bb * Hdim + jj] = __float2bfloat16_rn(hnew - __bfloat162float(hb));
                }
            }
        }
    }
}

// ---------------------------------------------------------------------------
extern "C" void kernel_launch(void* const* d_in, const int* in_sizes, int n_in,
                              void* d_out, int out_size)
{
    const float* C    = (const float*)d_in[0];
    const float* Q    = (const float*)d_in[1];
    const float* PM   = (const float*)d_in[2];
    const float* fc1w = (const float*)d_in[3];
    const float* fc1b = (const float*)d_in[4];
    const float* fc2w = (const float*)d_in[5];
    const float* fc2b = (const float*)d_in[6];
    const float* Wih  = (const float*)d_in[7];
    const float* Whh  = (const float*)d_in[8];
    const float* bih  = (const float*)d_in[9];
    const float* bhh  = (const float*)d_in[10];
    float* out = (float*)d_out;

    cudaFuncSetAttribute(xg_mma, cudaFuncAttributeMaxDynamicSharedMemorySize, 2 * XBUF);

    zero3_kernel<<<(Bdim*Hdim + 255)/256, 256>>>();
    split_C_kernel<<<32768, 256>>>(C);
    split_W_kernel<<<1536, 256>>>(Wih, Whh);
    kernel_G<<<Mrows/64, 256>>>(C, Q, PM, fc1w, fc1b, fc2w, fc2b);
    xg_mma<<<dim3(Mrows/128, H3/256), 512, 2 * XBUF>>>(bih);
    for (int s = 0; s < Sdim; s++) {
        gru_mma<<<dim3(Bdim/64, Hdim/64), 256>>>(
            bhh, s, s & 1, (s == Sdim - 1) ? out : nullptr);
    }
}

// round 5
// speedup vs baseline: 2.3480x; 1.9990x over previous
#include <cuda_runtime.h>
#include <cuda_fp16.h>
#include <math.h>
#include <stdint.h>

#define Hdim 512
#define SHdim 120
#define Bdim 1024
#define Sdim 64
#define H3 1536
#define H4 2048
#define Mrows (Bdim*Sdim)
#define LD 80          // padded smem row stride (bytes) for 32-k (64B) chunks
#define WLD 1040       // resident Whh row stride (512 halves = 1024B + 16 pad)

// ----------------------------- device scratch ------------------------------
__device__ float g_G[Sdim*Bdim];
__device__ float g_xg[(size_t)Sdim*Bdim*H3];
__device__ float g_hf[2][Bdim*Hdim];
__device__ __half g_h16hi[2][Bdim*Hdim];
__device__ __half g_h16lo[2][Bdim*Hdim];
__device__ __half g_C16hi[(size_t)Mrows*Hdim];
__device__ __half g_C16lo[(size_t)Mrows*Hdim];
__device__ __half g_Wih16[H3*Hdim];
__device__ __half g_Whh16[H3*Hdim];
__device__ __half g_fc1w16[128*H4];
__device__ unsigned g_bar_count;
__device__ unsigned g_bar_gen;

__device__ __forceinline__ float sigmoidf_(float x){ return 1.0f/(1.0f+expf(-x)); }

// ----------------------------- asm helpers ---------------------------------
__device__ __forceinline__ uint32_t smem_u32(const void* p){
    uint32_t a;
    asm("{ .reg .u64 t; cvta.to.shared.u64 t, %1; cvt.u32.u64 %0, t; }" : "=r"(a) : "l"(p));
    return a;
}
__device__ __forceinline__ void mma16816(float* c, uint32_t a0, uint32_t a1,
                                         uint32_t a2, uint32_t a3,
                                         uint32_t b0, uint32_t b1){
    asm volatile(
        "mma.sync.aligned.m16n8k16.row.col.f32.f16.f16.f32 "
        "{%0,%1,%2,%3},{%4,%5,%6,%7},{%8,%9},{%0,%1,%2,%3};"
        : "+f"(c[0]), "+f"(c[1]), "+f"(c[2]), "+f"(c[3])
        : "r"(a0), "r"(a1), "r"(a2), "r"(a3), "r"(b0), "r"(b1));
}
#define LDSM4(r0,r1,r2,r3, addr) \
    asm volatile("ldmatrix.sync.aligned.m8n8.x4.shared.b16 {%0,%1,%2,%3}, [%4];" \
        : "=r"(r0), "=r"(r1), "=r"(r2), "=r"(r3) : "r"(addr))
#define STS16(dst, v) asm volatile("st.shared.v4.b32 [%0],{%1,%2,%3,%4};" \
        :: "r"(dst), "r"((v).x), "r"((v).y), "r"((v).z), "r"((v).w))
#define STS8(dst, x, y) asm volatile("st.shared.v2.b32 [%0],{%1,%2};" \
        :: "r"(dst), "r"(x), "r"(y))
#define CP16(dst, src) asm volatile("cp.async.cg.shared.global [%0], [%1], 16;" \
        :: "r"(dst), "l"(src))
#define CP_COMMIT() asm volatile("cp.async.commit_group;" ::: "memory")
#define CP_WAIT2()  asm volatile("cp.async.wait_group 2;" ::: "memory")

// ----------------------------- init / convert ------------------------------
__global__ void zero_init_kernel(){
    int i = blockIdx.x * blockDim.x + threadIdx.x;
    if (i < Bdim * Hdim) {
        g_hf[0][i] = 0.0f;
        g_h16hi[0][i] = __float2half_rn(0.0f);
        g_h16lo[0][i] = __float2half_rn(0.0f);
    }
    if (i == 0) { g_bar_count = 0u; g_bar_gen = 0u; }
}

__device__ __forceinline__ void split4h(float4 v, uint2* hi, uint2* lo){
    __half2 h0(__float2half_rn(v.x), __float2half_rn(v.y));
    __half2 h1(__float2half_rn(v.z), __float2half_rn(v.w));
    __half2 l0(__float2half_rn(v.x - __half2float(h0.x)),
               __float2half_rn(v.y - __half2float(h0.y)));
    __half2 l1(__float2half_rn(v.z - __half2float(h1.x)),
               __float2half_rn(v.w - __half2float(h1.y)));
    hi->x = *(uint32_t*)&h0; hi->y = *(uint32_t*)&h1;
    lo->x = *(uint32_t*)&l0; lo->y = *(uint32_t*)&l1;
}
__global__ void split_C16_kernel(const float* __restrict__ src){
    size_t i = (size_t)blockIdx.x * blockDim.x + threadIdx.x;   // 8388608 float4
    uint2 h, l;
    split4h(((const float4*)src)[i], &h, &l);
    ((uint2*)g_C16hi)[i] = h;
    ((uint2*)g_C16lo)[i] = l;
}
__device__ __forceinline__ uint2 cvt4h(float4 v){
    __half2 h0(__float2half_rn(v.x), __float2half_rn(v.y));
    __half2 h1(__float2half_rn(v.z), __float2half_rn(v.w));
    uint2 o; o.x = *(uint32_t*)&h0; o.y = *(uint32_t*)&h1; return o;
}
__global__ void cvt_W16_kernel(const float* __restrict__ wih,
                               const float* __restrict__ whh,
                               const float* __restrict__ fc1w){
    int i = blockIdx.x * blockDim.x + threadIdx.x;   // 458752 total
    const int nW = H3 * Hdim / 4;                    // 196608
    const int nF = SHdim * H4 / 4;                   // 61440
    if (i < nW) {
        ((uint2*)g_Wih16)[i] = cvt4h(((const float4*)wih)[i]);
    } else if (i < 2*nW) {
        int j = i - nW;
        ((uint2*)g_Whh16)[j] = cvt4h(((const float4*)whh)[j]);
    } else if (i < 2*nW + nF) {
        int j = i - 2*nW;
        ((uint2*)g_fc1w16)[j] = cvt4h(((const float4*)fc1w)[j]);
    } else {
        int j = i - 2*nW - nF;                       // 4096 pad uint2
        ((uint2*)g_fc1w16)[nF + j] = make_uint2(0u, 0u);
    }
}

// ---------------------------------------------------------------------------
// Gate network via HMMA: G = sigmoid(fc2(tanh(feat @ fc1w^T + b)))
// CTA: m-tile 128, n full 128 (120 real), 256 threads (8 warps, wm=wid).
// K = 2048 over 64 chunks of 32; per chunk feat computed fp32 -> fp16 hi/lo.
// ---------------------------------------------------------------------------
#define GA2 10240                  // one A image (128 x LD)
#define GB2 10240                  // B image (128 x LD)
#define GBUF2 (2*GA2 + GB2)        // 30720 per stage

__device__ __forceinline__ void G_load(uint32_t buf, int tid, int m0, int c,
    const float* __restrict__ C, const float* __restrict__ Q,
    const float* __restrict__ PM){
    const int part = c >> 4;
    const int base0 = (c & 15) * 32;
    #pragma unroll
    for (int i = 0; i < 4; i++) {          // A: 1024 float4 of feat
        const int q = tid + i * 256;
        const int r = q >> 3, u = q & 7;
        const int mg = m0 + r;
        const float4 c4 = *(const float4*)(C + (size_t)mg * Hdim + base0 + u * 4);
        const int vrow = (mg >> 6) * Hdim + base0 + u * 4;
        const float4 v4 = (part == 0 || part == 2) ? *(const float4*)(Q + vrow)
                                                   : *(const float4*)(PM + vrow);
        float4 f;
        if (part < 2) { f.x=c4.x*v4.x; f.y=c4.y*v4.y; f.z=c4.z*v4.z; f.w=c4.w*v4.w; }
        else { f.x=fabsf(c4.x-v4.x); f.y=fabsf(c4.y-v4.y); f.z=fabsf(c4.z-v4.z); f.w=fabsf(c4.w-v4.w); }
        uint2 h, l;
        split4h(f, &h, &l);
        STS8(buf + r * LD + u * 8, h.x, h.y);
        STS8(buf + GA2 + r * LD + u * 8, l.x, l.y);
    }
    #pragma unroll
    for (int i = 0; i < 2; i++) {          // B: 512 uint4 of fc1w16
        const int q = tid + i * 256;
        const int r = q >> 2, u = q & 3;
        uint4 v = *(const uint4*)(g_fc1w16 + (size_t)r * H4 + part * 512 + base0 + u * 8);
        STS16(buf + 2 * GA2 + r * LD + u * 16, v);
    }
}

__global__ __launch_bounds__(256, 1) void G_mma(
    const float* __restrict__ C, const float* __restrict__ Q,
    const float* __restrict__ PM,
    const float* __restrict__ fc1b, const float* __restrict__ fc2w,
    const float* __restrict__ fc2b)
{
    extern __shared__ __align__(16) char smg2[];
    const uint32_t sb = smem_u32(smg2);
    const int tid = threadIdx.x, lane = tid & 31, wm = tid >> 5;
    const int m0 = blockIdx.x * 128;

    float acc[16][4];
    #pragma unroll
    for (int a = 0; a < 16; a++)
        #pragma unroll
        for (int d = 0; d < 4; d++) acc[a][d] = 0.0f;

    G_load(sb, tid, m0, 0, C, Q, PM);
    __syncthreads();

    const uint32_t a_lrow = (wm * 16 + (lane & 15)) * LD + (lane >> 4) * 16;
    const uint32_t b_lrow = ((lane >> 4) * 8 + (lane & 7)) * LD + ((lane >> 3) & 1) * 16;

    for (int c = 0; c < 64; c++) {
        const uint32_t cur = sb + (c & 1) * GBUF2;
        if (c + 1 < 64) G_load(sb + ((c + 1) & 1) * GBUF2, tid, m0, c + 1, C, Q, PM);
        #pragma unroll
        for (int kk = 0; kk < 2; kk++) {
            uint32_t b[8][4];
            #pragma unroll
            for (int nb = 0; nb < 8; nb++)
                LDSM4(b[nb][0], b[nb][1], b[nb][2], b[nb][3],
                      cur + 2*GA2 + (nb * 16) * LD + kk * 32 + b_lrow);
            #pragma unroll
            for (int t = 0; t < 2; t++) {
                uint32_t a0, a1, a2, a3;
                LDSM4(a0, a1, a2, a3, cur + t * GA2 + a_lrow + kk * 32);
                #pragma unroll
                for (int nb = 0; nb < 8; nb++) {
                    mma16816(acc[nb*2],   a0, a1, a2, a3, b[nb][0], b[nb][1]);
                    mma16816(acc[nb*2+1], a0, a1, a2, a3, b[nb][2], b[nb][3]);
                }
            }
        }
        __syncthreads();
    }

    const float fc2b0 = fc2b[0];
    #pragma unroll
    for (int half = 0; half < 2; half++) {
        float partial = 0.0f;
        #pragma unroll
        for (int nb = 0; nb < 16; nb++) {
            #pragma unroll
            for (int cc = 0; cc < 2; cc++) {
                const int n = nb * 8 + (lane & 3) * 2 + cc;
                if (n < SHdim)
                    partial += fc2w[n] * tanhf(acc[nb][half*2+cc] + fc1b[n]);
            }
        }
        partial += __shfl_xor_sync(0xffffffffu, partial, 1);
        partial += __shfl_xor_sync(0xffffffffu, partial, 2);
        if ((lane & 3) == 0) {
            const int m = m0 + wm * 16 + (lane >> 2) + half * 8;
            g_G[(m & 63) * Bdim + (m >> 6)] = sigmoidf_(partial + fc2b0);
        }
    }
}

// ---------------------------------------------------------------------------
// xg = C @ Wih^T + b via fp16 HMMA (2 terms). CTA 128m x 256n, 512 threads.
// ---------------------------------------------------------------------------
#define XA_SZ (128*LD)
#define XB_SZ (256*LD)
#define XBUF  (XA_SZ + XB_SZ)

__device__ __forceinline__ void xg_load(uint32_t buf, int tid, int m0, int n0, int c){
    const __half* __restrict__ Asrc = (c < 16) ? g_C16hi : g_C16lo;
    const int k0 = (c & 15) * 32;
    {
        const int u = tid & 3, r = tid >> 2;
        uint4 v = *(const uint4*)(Asrc + (size_t)(m0 + r) * Hdim + k0 + u * 8);
        STS16(buf + r * LD + u * 16, v);
    }
    #pragma unroll
    for (int i = 0; i < 2; i++) {
        const int q = tid + i * 512;
        const int u = q & 3, r = q >> 2;
        uint4 v = *(const uint4*)(g_Wih16 + (size_t)(n0 + r) * Hdim + k0 + u * 8);
        STS16(buf + XA_SZ + r * LD + u * 16, v);
    }
}

__global__ __launch_bounds__(512, 1) void xg_mma(const float* __restrict__ bih)
{
    extern __shared__ __align__(16) char smx[];
    const uint32_t sb = smem_u32(smx);
    const int tid = threadIdx.x, lane = tid & 31, wid = tid >> 5;
    const int wm = wid >> 3, wn = wid & 7;
    const int m0 = blockIdx.x * 128, n0 = blockIdx.y * 256;

    float acc[4][4][4];
    #pragma unroll
    for (int a = 0; a < 4; a++)
        #pragma unroll
        for (int b = 0; b < 4; b++)
            #pragma unroll
            for (int d = 0; d < 4; d++) acc[a][b][d] = 0.0f;

    xg_load(sb, tid, m0, n0, 0);
    __syncthreads();

    const uint32_t a_lrow = (lane & 15) * LD + (lane >> 4) * 16;
    const uint32_t b_lrow = ((lane >> 4) * 8 + (lane & 7)) * LD + ((lane >> 3) & 1) * 16;

    for (int c = 0; c < 32; c++) {
        const uint32_t cur = sb + (c & 1) * XBUF;
        if (c + 1 < 32) xg_load(sb + ((c + 1) & 1) * XBUF, tid, m0, n0, c + 1);
        #pragma unroll
        for (int kk = 0; kk < 2; kk++) {
            uint32_t a[4][4];
            #pragma unroll
            for (int mf = 0; mf < 4; mf++)
                LDSM4(a[mf][0], a[mf][1], a[mf][2], a[mf][3],
                      cur + (wm * 64 + mf * 16) * LD + kk * 32 + a_lrow);
            #pragma unroll
            for (int nfp = 0; nfp < 2; nfp++) {
                uint32_t b0, b1, b2, b3;
                LDSM4(b0, b1, b2, b3,
                      cur + XA_SZ + (wn * 32 + nfp * 16) * LD + kk * 32 + b_lrow);
                #pragma unroll
                for (int mf = 0; mf < 4; mf++) {
                    mma16816(acc[mf][nfp*2],   a[mf][0], a[mf][1], a[mf][2], a[mf][3], b0, b1);
                    mma16816(acc[mf][nfp*2+1], a[mf][0], a[mf][1], a[mf][2], a[mf][3], b2, b3);
                }
            }
        }
        __syncthreads();
    }

    #pragma unroll
    for (int mf = 0; mf < 4; mf++) {
        #pragma unroll
        for (int half = 0; half < 2; half++) {
            const int m = m0 + wm * 64 + mf * 16 + (lane >> 2) + half * 8;
            const size_t ob = ((size_t)(m & 63) * Bdim + (m >> 6)) * H3;
            #pragma unroll
            for (int nf = 0; nf < 4; nf++) {
                const int jj = n0 + wn * 32 + nf * 8 + (lane & 3) * 2;
                float2 o;
                o.x = acc[mf][nf][half*2+0] + bih[jj];
                o.y = acc[mf][nf][half*2+1] + bih[jj+1];
                *(float2*)(g_xg + ob + jj) = o;
            }
        }
    }
}

// ---------------------------------------------------------------------------
// Persistent GRU: 128 CTAs (16 batch-tiles x 8 j-tiles), Whh resident in smem,
// h streamed via cp.async, grid barrier between steps.
// ---------------------------------------------------------------------------
#define WB_SZ (192*WLD)            // 199680
#define GABUF (64*LD)              // 5120 per stage, 4 stages
#define GRU_SMEM (WB_SZ + 4*GABUF) // 220160

__device__ __forceinline__ void gru_ldA(uint32_t dst, int tid, int b0, int c,
                                        const __half* __restrict__ hhi,
                                        const __half* __restrict__ hlo){
    const __half* __restrict__ src = (c < 16) ? hhi : hlo;
    const int k0 = (c & 15) * 32;
    const int u = tid & 3, r = tid >> 2;     // 64 rows x 4 uint4
    CP16(dst + r * LD + u * 16, src + (size_t)(b0 + r) * Hdim + k0 + u * 8);
}

__global__ __launch_bounds__(256, 1) void gru_pers(
    const float* __restrict__ bhh, float* __restrict__ outp)
{
    extern __shared__ __align__(16) char smp[];
    const uint32_t sb = smem_u32(smp);
    const uint32_t WB = sb;
    const uint32_t AB = sb + WB_SZ;
    const int tid = threadIdx.x, lane = tid & 31, wid = tid >> 5;
    const int wm = wid >> 1, wn = wid & 1;
    const int b0 = blockIdx.x * 64, j0 = blockIdx.y * 64;

    // Load resident Whh fp16 tile: 192 rows x 512 halves
    for (int q = tid; q < 12288; q += 256) {
        const int r = q >> 6, u = q & 63;
        const int g = r >> 6, jj = r & 63;
        uint4 v = *(const uint4*)(g_Whh16 + (size_t)((g << 9) + j0 + jj) * Hdim + u * 8);
        STS16(WB + r * WLD + u * 16, v);
    }
    __syncthreads();

    const uint32_t a_lrow = (wm * 16 + (lane & 15)) * LD + (lane >> 4) * 16;
    const uint32_t b_lrowW = ((lane >> 4) * 8 + (lane & 7)) * WLD + ((lane >> 3) & 1) * 16;

    for (int s = 0; s < Sdim; s++) {
        const int par = s & 1;
        const __half* __restrict__ hhi = g_h16hi[par];
        const __half* __restrict__ hlo = g_h16lo[par];

        float acc[3][4][4];
        #pragma unroll
        for (int g = 0; g < 3; g++)
            #pragma unroll
            for (int b = 0; b < 4; b++)
                #pragma unroll
                for (int d = 0; d < 4; d++) acc[g][b][d] = 0.0f;

        #pragma unroll
        for (int c = 0; c < 3; c++) {
            gru_ldA(AB + (c & 3) * GABUF, tid, b0, c, hhi, hlo);
            CP_COMMIT();
        }

        for (int c = 0; c < 32; c++) {
            CP_WAIT2();
            __syncthreads();
            const uint32_t cur = AB + (c & 3) * GABUF;
            const uint32_t koff = (c & 15) * 64;
            #pragma unroll
            for (int kk = 0; kk < 2; kk++) {
                uint32_t a0, a1, a2, a3;
                LDSM4(a0, a1, a2, a3, cur + a_lrow + kk * 32);
                #pragma unroll
                for (int g = 0; g < 3; g++) {
                    #pragma unroll
                    for (int nfp = 0; nfp < 2; nfp++) {
                        uint32_t b0r, b1r, b2r, b3r;
                        LDSM4(b0r, b1r, b2r, b3r,
                              WB + (g * 64 + wn * 32 + nfp * 16) * WLD + koff + kk * 32 + b_lrowW);
                        mma16816(acc[g][nfp*2],   a0, a1, a2, a3, b0r, b1r);
                        mma16816(acc[g][nfp*2+1], a0, a1, a2, a3, b2r, b3r);
                    }
                }
            }
            if (c + 3 < 32) gru_ldA(AB + ((c + 3) & 3) * GABUF, tid, b0, c + 3, hhi, hlo);
            CP_COMMIT();
        }

        // epilogue
        const float* __restrict__ xg_s = g_xg + (size_t)s * Bdim * H3;
        const int last = (s == Sdim - 1);
        float* __restrict__ hout = last ? outp : g_hf[par ^ 1];
        __half* __restrict__ hhiN = g_h16hi[par ^ 1];
        __half* __restrict__ hloN = g_h16lo[par ^ 1];

        #pragma unroll
        for (int half = 0; half < 2; half++) {
            const int bb = b0 + wm * 16 + (lane >> 2) + half * 8;
            const float gate = g_G[s * Bdim + bb];
            const float* __restrict__ xrow = xg_s + (size_t)bb * H3;
            const float* __restrict__ hrow = g_hf[par] + bb * Hdim;
            #pragma unroll
            for (int nf = 0; nf < 4; nf++) {
                #pragma unroll
                for (int cc = 0; cc < 2; cc++) {
                    const int jj = j0 + wn * 32 + nf * 8 + (lane & 3) * 2 + cc;
                    const int ai = half * 2 + cc;
                    const float hr = acc[0][nf][ai] + bhh[jj];
                    const float hz = acc[1][nf][ai] + bhh[Hdim + jj];
                    const float hn = acc[2][nf][ai] + bhh[2 * Hdim + jj];
                    const float r = sigmoidf_(xrow[jj] + hr);
                    const float z = sigmoidf_(xrow[Hdim + jj] + hz);
                    const float n = tanhf(xrow[2 * Hdim + jj] + r * hn);
                    const float hold = hrow[jj];
                    const float hnew = gate * ((1.0f - z) * n + z * hold) + (1.0f - gate) * hold;
                    hout[bb * Hdim + jj] = hnew;
                    if (!last) {
                        const __half hb = __float2half_rn(hnew);
                        hhiN[bb * Hdim + jj] = hb;
                        hloN[bb * Hdim + jj] = __float2half_rn(hnew - __half2float(hb));
                    }
                }
            }
        }

        // grid-wide barrier (skip after last step)
        if (!last) {
            __syncthreads();
            if (tid == 0) {
                __threadfence();
                const unsigned target = (unsigned)(s + 1);
                unsigned arr = atomicAdd(&g_bar_count, 1u);
                if (arr == 127u) {
                    g_bar_count = 0u;
                    atomicExch(&g_bar_gen, target);
                } else {
                    while (atomicAdd(&g_bar_gen, 0u) < target) {}
                }
                __threadfence();
            }
            __syncthreads();
        }
    }
}

// ---------------------------------------------------------------------------
extern "C" void kernel_launch(void* const* d_in, const int* in_sizes, int n_in,
                              void* d_out, int out_size)
{
    const float* C    = (const float*)d_in[0];
    const float* Q    = (const float*)d_in[1];
    const float* PM   = (const float*)d_in[2];
    const float* fc1w = (const float*)d_in[3];
    const float* fc1b = (const float*)d_in[4];
    const float* fc2w = (const float*)d_in[5];
    const float* fc2b = (const float*)d_in[6];
    const float* Wih  = (const float*)d_in[7];
    const float* Whh  = (const float*)d_in[8];
    const float* bih  = (const float*)d_in[9];
    const float* bhh  = (const float*)d_in[10];
    float* out = (float*)d_out;

    static int configured = 0;
    if (!configured) {
        cudaFuncSetAttribute(G_mma,   cudaFuncAttributeMaxDynamicSharedMemorySize, 2 * GBUF2);
        cudaFuncSetAttribute(xg_mma,  cudaFuncAttributeMaxDynamicSharedMemorySize, 2 * XBUF);
        cudaFuncSetAttribute(gru_pers, cudaFuncAttributeMaxDynamicSharedMemorySize, GRU_SMEM);
        configured = 1;
    }

    zero_init_kernel<<<(Bdim*Hdim + 255)/256, 256>>>();
    split_C16_kernel<<<32768, 256>>>(C);
    cvt_W16_kernel<<<1792, 256>>>(Wih, Whh, fc1w);
    G_mma<<<Mrows/128, 256, 2 * GBUF2>>>(C, Q, PM, fc1b, fc2w, fc2b);
    xg_mma<<<dim3(Mrows/128, H3/256), 512, 2 * XBUF>>>(bih);
    gru_pers<<<dim3(Bdim/64, Hdim/64), 256, GRU_SMEM>>>(bhh, out);
}

// round 6
// speedup vs baseline: 2.7706x; 1.1799x over previous
#include <cuda_runtime.h>
#include <cuda_fp16.h>
#include <math.h>
#include <stdint.h>

#define Hdim 512
#define SHdim 120
#define Bdim 1024
#define Sdim 64
#define H3 1536
#define H4 2048
#define Mrows (Bdim*Sdim)
#define LD 80          // 32-half (64B) rows + 16B pad
#define LD64 144       // 64-half (128B) rows + 16B pad
#define WLD 1040       // resident Whh rows: 512 halves (1024B) + 16B pad

// ----------------------------- device scratch ------------------------------
__device__ float g_G[Sdim*Bdim];
__device__ float g_xg[(size_t)Sdim*Bdim*H3];
__device__ __half g_h16hi[2][Bdim*Hdim];
__device__ __half g_h16lo[2][Bdim*Hdim];
__device__ __half g_C16hi[(size_t)Mrows*Hdim];
__device__ __half g_C16lo[(size_t)Mrows*Hdim];
__device__ __half g_Wih16[H3*Hdim];
__device__ __half g_Whh16[H3*Hdim];
__device__ __half g_fc1w16[128*H4];
__device__ unsigned g_bar_count;
__device__ unsigned g_bar_gen;

__device__ __forceinline__ float sigmoidf_(float x){ return 1.0f/(1.0f+expf(-x)); }

// ----------------------------- asm helpers ---------------------------------
__device__ __forceinline__ uint32_t smem_u32(const void* p){
    uint32_t a;
    asm("{ .reg .u64 t; cvta.to.shared.u64 t, %1; cvt.u32.u64 %0, t; }" : "=r"(a) : "l"(p));
    return a;
}
__device__ __forceinline__ void mma16816(float* c, uint32_t a0, uint32_t a1,
                                         uint32_t a2, uint32_t a3,
                                         uint32_t b0, uint32_t b1){
    asm volatile(
        "mma.sync.aligned.m16n8k16.row.col.f32.f16.f16.f32 "
        "{%0,%1,%2,%3},{%4,%5,%6,%7},{%8,%9},{%0,%1,%2,%3};"
        : "+f"(c[0]), "+f"(c[1]), "+f"(c[2]), "+f"(c[3])
        : "r"(a0), "r"(a1), "r"(a2), "r"(a3), "r"(b0), "r"(b1));
}
#define LDSM4(r0,r1,r2,r3, addr) \
    asm volatile("ldmatrix.sync.aligned.m8n8.x4.shared.b16 {%0,%1,%2,%3}, [%4];" \
        : "=r"(r0), "=r"(r1), "=r"(r2), "=r"(r3) : "r"(addr))
#define STS16(dst, v) asm volatile("st.shared.v4.b32 [%0],{%1,%2,%3,%4};" \
        :: "r"(dst), "r"((v).x), "r"((v).y), "r"((v).z), "r"((v).w))
#define STS8(dst, x, y) asm volatile("st.shared.v2.b32 [%0],{%1,%2};" \
        :: "r"(dst), "r"(x), "r"(y))
#define CP16(dst, src) asm volatile("cp.async.cg.shared.global [%0], [%1], 16;" \
        :: "r"(dst), "l"(src))
#define CP_COMMIT() asm volatile("cp.async.commit_group;" ::: "memory")
#define CP_WAIT0()  asm volatile("cp.async.wait_group 0;" ::: "memory")
#define CP_WAIT1()  asm volatile("cp.async.wait_group 1;" ::: "memory")

// ----------------------------- init / convert ------------------------------
__global__ void zero_init_kernel(){
    int i = blockIdx.x * blockDim.x + threadIdx.x;
    if (i < Bdim * Hdim) {
        g_h16hi[0][i] = __float2half_rn(0.0f);
        g_h16lo[0][i] = __float2half_rn(0.0f);
    }
    if (i == 0) { g_bar_count = 0u; g_bar_gen = 0u; }
}
__device__ __forceinline__ void split4h(float4 v, uint2* hi, uint2* lo){
    __half2 h0(__float2half_rn(v.x), __float2half_rn(v.y));
    __half2 h1(__float2half_rn(v.z), __float2half_rn(v.w));
    __half2 l0(__float2half_rn(v.x - __half2float(h0.x)),
               __float2half_rn(v.y - __half2float(h0.y)));
    __half2 l1(__float2half_rn(v.z - __half2float(h1.x)),
               __float2half_rn(v.w - __half2float(h1.y)));
    hi->x = *(uint32_t*)&h0; hi->y = *(uint32_t*)&h1;
    lo->x = *(uint32_t*)&l0; lo->y = *(uint32_t*)&l1;
}
__global__ void split_C16_kernel(const float* __restrict__ src){
    size_t i = (size_t)blockIdx.x * blockDim.x + threadIdx.x;   // 8388608 float4
    uint2 h, l;
    split4h(((const float4*)src)[i], &h, &l);
    ((uint2*)g_C16hi)[i] = h;
    ((uint2*)g_C16lo)[i] = l;
}
__device__ __forceinline__ uint2 cvt4h(float4 v){
    __half2 h0(__float2half_rn(v.x), __float2half_rn(v.y));
    __half2 h1(__float2half_rn(v.z), __float2half_rn(v.w));
    uint2 o; o.x = *(uint32_t*)&h0; o.y = *(uint32_t*)&h1; return o;
}
__global__ void cvt_W16_kernel(const float* __restrict__ wih,
                               const float* __restrict__ whh,
                               const float* __restrict__ fc1w){
    int i = blockIdx.x * blockDim.x + threadIdx.x;
    const int nW = H3 * Hdim / 4;                    // 196608
    const int nF = SHdim * H4 / 4;                   // 61440
    if (i < nW) {
        ((uint2*)g_Wih16)[i] = cvt4h(((const float4*)wih)[i]);
    } else if (i < 2*nW) {
        int j = i - nW;
        ((uint2*)g_Whh16)[j] = cvt4h(((const float4*)whh)[j]);
    } else if (i < 2*nW + nF) {
        int j = i - 2*nW;
        ((uint2*)g_fc1w16)[j] = cvt4h(((const float4*)fc1w)[j]);
    } else {
        int j = i - 2*nW - nF;                       // 4096 pad uint2
        ((uint2*)g_fc1w16)[nF + j] = make_uint2(0u, 0u);
    }
}

// ---------------------------------------------------------------------------
// Gate network: feat fp16(hi) @ fc1w16^T, pipelined (A register-staged, B cp.async)
// CTA m-tile 128, n 128 (120 real), 256 threads; 64 chunks of k32.
// ---------------------------------------------------------------------------
#define GA2 (128*LD)               // 10240
#define GST (2*GA2)                // stage = A + B = 20480

__device__ __forceinline__ void G_fetch(int tid, int m0, int c,
    const float* __restrict__ C, const float* __restrict__ Q,
    const float* __restrict__ PM, float4* rc, float4* rv){
    const int part = c >> 4;
    const int base0 = (c & 15) * 32;
    #pragma unroll
    for (int i = 0; i < 4; i++) {
        const int q = tid + i * 256;
        const int r = q >> 3, u = q & 7;
        const int mg = m0 + r;
        rc[i] = *(const float4*)(C + (size_t)mg * Hdim + base0 + u * 4);
        const int vrow = (mg >> 6) * Hdim + base0 + u * 4;
        rv[i] = (part == 0 || part == 2) ? *(const float4*)(Q + vrow)
                                         : *(const float4*)(PM + vrow);
    }
}
__device__ __forceinline__ void G_store(int tid, int c, uint32_t buf,
                                        const float4* rc, const float4* rv){
    const int part = c >> 4;
    #pragma unroll
    for (int i = 0; i < 4; i++) {
        const int q = tid + i * 256;
        const int r = q >> 3, u = q & 7;
        const float4 c4 = rc[i], v4 = rv[i];
        float4 f;
        if (part < 2) { f.x=c4.x*v4.x; f.y=c4.y*v4.y; f.z=c4.z*v4.z; f.w=c4.w*v4.w; }
        else { f.x=fabsf(c4.x-v4.x); f.y=fabsf(c4.y-v4.y); f.z=fabsf(c4.z-v4.z); f.w=fabsf(c4.w-v4.w); }
        uint2 h = cvt4h(f);
        STS8(buf + r * LD + u * 8, h.x, h.y);
    }
}
__device__ __forceinline__ void G_cpB(int tid, int c, uint32_t buf){
    const int part = c >> 4;
    const int base0 = (c & 15) * 32;
    #pragma unroll
    for (int i = 0; i < 2; i++) {
        const int q = tid + i * 256;
        const int r = q >> 2, u = q & 3;
        CP16(buf + GA2 + r * LD + u * 16,
             g_fc1w16 + (size_t)r * H4 + part * 512 + base0 + u * 8);
    }
}

__global__ __launch_bounds__(256, 1) void G_mma(
    const float* __restrict__ C, const float* __restrict__ Q,
    const float* __restrict__ PM,
    const float* __restrict__ fc1b, const float* __restrict__ fc2w,
    const float* __restrict__ fc2b)
{
    extern __shared__ __align__(16) char smg2[];
    const uint32_t sb = smem_u32(smg2);
    const int tid = threadIdx.x, lane = tid & 31, wm = tid >> 5;
    const int m0 = blockIdx.x * 128;

    float acc[16][4];
    #pragma unroll
    for (int a = 0; a < 16; a++)
        #pragma unroll
        for (int d = 0; d < 4; d++) acc[a][d] = 0.0f;

    float4 rc[4], rv[4];
    G_fetch(tid, m0, 0, C, Q, PM, rc, rv);
    G_cpB(tid, 0, sb);
    CP_COMMIT();
    G_store(tid, 0, sb, rc, rv);
    CP_WAIT0();
    __syncthreads();

    const uint32_t a_lrow = (wm * 16 + (lane & 15)) * LD + (lane >> 4) * 16;
    const uint32_t b_lrow = ((lane >> 4) * 8 + (lane & 7)) * LD + ((lane >> 3) & 1) * 16;

    for (int c = 0; c < 64; c++) {
        const uint32_t cur = sb + (c & 1) * GST;
        const uint32_t nxt = sb + ((c + 1) & 1) * GST;
        if (c < 63) {
            G_fetch(tid, m0, c + 1, C, Q, PM, rc, rv);
            G_cpB(tid, c + 1, nxt);
        }
        CP_COMMIT();
        #pragma unroll
        for (int kk = 0; kk < 2; kk++) {
            uint32_t b[8][4];
            #pragma unroll
            for (int nb = 0; nb < 8; nb++)
                LDSM4(b[nb][0], b[nb][1], b[nb][2], b[nb][3],
                      cur + GA2 + (nb * 16) * LD + kk * 32 + b_lrow);
            uint32_t a0, a1, a2, a3;
            LDSM4(a0, a1, a2, a3, cur + a_lrow + kk * 32);
            #pragma unroll
            for (int nb = 0; nb < 8; nb++) {
                mma16816(acc[nb*2],   a0, a1, a2, a3, b[nb][0], b[nb][1]);
                mma16816(acc[nb*2+1], a0, a1, a2, a3, b[nb][2], b[nb][3]);
            }
        }
        if (c < 63) G_store(tid, c + 1, nxt, rc, rv);
        CP_WAIT0();
        __syncthreads();
    }

    const float fc2b0 = fc2b[0];
    #pragma unroll
    for (int half = 0; half < 2; half++) {
        float partial = 0.0f;
        #pragma unroll
        for (int nb = 0; nb < 16; nb++) {
            #pragma unroll
            for (int cc = 0; cc < 2; cc++) {
                const int n = nb * 8 + (lane & 3) * 2 + cc;
                if (n < SHdim)
                    partial += fc2w[n] * tanhf(acc[nb][half*2+cc] + fc1b[n]);
            }
        }
        partial += __shfl_xor_sync(0xffffffffu, partial, 1);
        partial += __shfl_xor_sync(0xffffffffu, partial, 2);
        if ((lane & 3) == 0) {
            const int m = m0 + wm * 16 + (lane >> 2) + half * 8;
            g_G[(m & 63) * Bdim + (m >> 6)] = sigmoidf_(partial + fc2b0);
        }
    }
}

// ---------------------------------------------------------------------------
// xg = C @ Wih^T + b. CTA 128m x 256n, 512 threads, cp.async 3-stage, k64.
// 16 chunks: c<8 hi (k0=c*64), c>=8 lo.
// ---------------------------------------------------------------------------
#define XA2 (128*LD64)             // 18432
#define XST (XA2 + 256*LD64)       // 55296

__device__ __forceinline__ void xg_ld(uint32_t buf, int tid, int m0, int n0, int c){
    const __half* __restrict__ Asrc = (c < 8) ? g_C16hi : g_C16lo;
    const int k0 = (c & 7) * 64;
    #pragma unroll
    for (int i = 0; i < 2; i++) {            // A: 1024 u4
        const int q = tid + i * 512;
        const int r = q >> 3, u = q & 7;
        CP16(buf + r * LD64 + u * 16, Asrc + (size_t)(m0 + r) * Hdim + k0 + u * 8);
    }
    #pragma unroll
    for (int i = 0; i < 4; i++) {            // B: 2048 u4
        const int q = tid + i * 512;
        const int r = q >> 3, u = q & 7;
        CP16(buf + XA2 + r * LD64 + u * 16, g_Wih16 + (size_t)(n0 + r) * Hdim + k0 + u * 8);
    }
}

__global__ __launch_bounds__(512, 1) void xg_mma(const float* __restrict__ bih)
{
    extern __shared__ __align__(16) char smx[];
    const uint32_t sb = smem_u32(smx);
    const int tid = threadIdx.x, lane = tid & 31, wid = tid >> 5;
    const int wm = wid >> 3, wn = wid & 7;
    const int m0 = blockIdx.x * 128, n0 = blockIdx.y * 256;

    float acc[4][4][4];
    #pragma unroll
    for (int a = 0; a < 4; a++)
        #pragma unroll
        for (int b = 0; b < 4; b++)
            #pragma unroll
            for (int d = 0; d < 4; d++) acc[a][b][d] = 0.0f;

    xg_ld(sb, tid, m0, n0, 0); CP_COMMIT();
    xg_ld(sb + XST, tid, m0, n0, 1); CP_COMMIT();

    const uint32_t a_lrow = (lane & 15) * LD64 + (lane >> 4) * 16;
    const uint32_t b_lrow = ((lane >> 4) * 8 + (lane & 7)) * LD64 + ((lane >> 3) & 1) * 16;

    for (int c = 0; c < 16; c++) {
        CP_WAIT1();
        __syncthreads();
        if (c + 2 < 16) xg_ld(sb + ((c + 2) % 3) * XST, tid, m0, n0, c + 2);
        CP_COMMIT();
        const uint32_t cur = sb + (c % 3) * XST;
        #pragma unroll
        for (int kk = 0; kk < 4; kk++) {
            uint32_t a[4][4];
            #pragma unroll
            for (int mf = 0; mf < 4; mf++)
                LDSM4(a[mf][0], a[mf][1], a[mf][2], a[mf][3],
                      cur + (wm * 64 + mf * 16) * LD64 + kk * 32 + a_lrow);
            #pragma unroll
            for (int nfp = 0; nfp < 2; nfp++) {
                uint32_t b0, b1, b2, b3;
                LDSM4(b0, b1, b2, b3,
                      cur + XA2 + (wn * 32 + nfp * 16) * LD64 + kk * 32 + b_lrow);
                #pragma unroll
                for (int mf = 0; mf < 4; mf++) {
                    mma16816(acc[mf][nfp*2],   a[mf][0], a[mf][1], a[mf][2], a[mf][3], b0, b1);
                    mma16816(acc[mf][nfp*2+1], a[mf][0], a[mf][1], a[mf][2], a[mf][3], b2, b3);
                }
            }
        }
    }

    #pragma unroll
    for (int mf = 0; mf < 4; mf++) {
        #pragma unroll
        for (int half = 0; half < 2; half++) {
            const int m = m0 + wm * 64 + mf * 16 + (lane >> 2) + half * 8;
            const size_t ob = ((size_t)(m & 63) * Bdim + (m >> 6)) * H3;
            #pragma unroll
            for (int nf = 0; nf < 4; nf++) {
                const int jj = n0 + wn * 32 + nf * 8 + (lane & 3) * 2;
                float2 o;
                o.x = acc[mf][nf][half*2+0] + bih[jj];
                o.y = acc[mf][nf][half*2+1] + bih[jj+1];
                *(float2*)(g_xg + ob + jj) = o;
            }
        }
    }
}

// ---------------------------------------------------------------------------
// Persistent GRU: Whh resident, h via cp.async 3-stage k64 (16 chunks/step).
// ---------------------------------------------------------------------------
#define WB_SZ (192*WLD)            // 199680
#define GAST (64*LD64)             // 9216/stage, 3 stages
#define GRU_SMEM (WB_SZ + 3*GAST)  // 227328

__device__ __forceinline__ void gru_ldA(uint32_t dst, int tid, int b0, int c,
                                        const __half* __restrict__ hhi,
                                        const __half* __restrict__ hlo){
    const __half* __restrict__ src = (c < 8) ? hhi : hlo;
    const int k0 = (c & 7) * 64;
    #pragma unroll
    for (int i = 0; i < 2; i++) {            // 512 u4
        const int q = tid + i * 256;
        const int r = q >> 3, u = q & 7;
        CP16(dst + r * LD64 + u * 16, src + (size_t)(b0 + r) * Hdim + k0 + u * 8);
    }
}

__global__ __launch_bounds__(256, 1) void gru_pers(
    const float* __restrict__ bhh, float* __restrict__ outp)
{
    extern __shared__ __align__(16) char smp[];
    const uint32_t sb = smem_u32(smp);
    const uint32_t WB = sb;
    const uint32_t AB = sb + WB_SZ;
    const int tid = threadIdx.x, lane = tid & 31, wid = tid >> 5;
    const int wm = wid >> 1, wn = wid & 1;
    const int b0 = blockIdx.x * 64, j0 = blockIdx.y * 64;

    // resident Whh: 192 rows x 512 halves
    for (int q = tid; q < 12288; q += 256) {
        const int r = q >> 6, u = q & 63;
        const int g = r >> 6, jj = r & 63;
        uint4 v = *(const uint4*)(g_Whh16 + (size_t)((g << 9) + j0 + jj) * Hdim + u * 8);
        STS16(WB + r * WLD + u * 16, v);
    }
    __syncthreads();

    const uint32_t a_lrow = (wm * 16 + (lane & 15)) * LD64 + (lane >> 4) * 16;
    const uint32_t b_lrowW = ((lane >> 4) * 8 + (lane & 7)) * WLD + ((lane >> 3) & 1) * 16;

    for (int s = 0; s < Sdim; s++) {
        const int par = s & 1;
        const __half* __restrict__ hhi = g_h16hi[par];
        const __half* __restrict__ hlo = g_h16lo[par];

        float acc[3][4][4];
        #pragma unroll
        for (int g = 0; g < 3; g++)
            #pragma unroll
            for (int b = 0; b < 4; b++)
                #pragma unroll
                for (int d = 0; d < 4; d++) acc[g][b][d] = 0.0f;

        gru_ldA(AB, tid, b0, 0, hhi, hlo); CP_COMMIT();
        gru_ldA(AB + GAST, tid, b0, 1, hhi, hlo); CP_COMMIT();

        for (int c = 0; c < 16; c++) {
            CP_WAIT1();
            __syncthreads();
            if (c + 2 < 16) gru_ldA(AB + ((c + 2) % 3) * GAST, tid, b0, c + 2, hhi, hlo);
            CP_COMMIT();
            const uint32_t cur = AB + (c % 3) * GAST;
            const uint32_t koff = (c & 7) * 128;
            #pragma unroll
            for (int kk = 0; kk < 4; kk++) {
                uint32_t a0, a1, a2, a3;
                LDSM4(a0, a1, a2, a3, cur + a_lrow + kk * 32);
                #pragma unroll
                for (int g = 0; g < 3; g++) {
                    #pragma unroll
                    for (int nfp = 0; nfp < 2; nfp++) {
                        uint32_t b0r, b1r, b2r, b3r;
                        LDSM4(b0r, b1r, b2r, b3r,
                              WB + (g * 64 + wn * 32 + nfp * 16) * WLD + koff + kk * 32 + b_lrowW);
                        mma16816(acc[g][nfp*2],   a0, a1, a2, a3, b0r, b1r);
                        mma16816(acc[g][nfp*2+1], a0, a1, a2, a3, b2r, b3r);
                    }
                }
            }
        }

        // epilogue
        const float* __restrict__ xg_s = g_xg + (size_t)s * Bdim * H3;
        const int last = (s == Sdim - 1);
        __half* __restrict__ hhiN = g_h16hi[par ^ 1];
        __half* __restrict__ hloN = g_h16lo[par ^ 1];

        #pragma unroll
        for (int half = 0; half < 2; half++) {
            const int bb = b0 + wm * 16 + (lane >> 2) + half * 8;
            const float gate = g_G[s * Bdim + bb];
            const float* __restrict__ xrow = xg_s + (size_t)bb * H3;
            const __half* __restrict__ hhr = hhi + bb * Hdim;
            const __half* __restrict__ hlr = hlo + bb * Hdim;
            #pragma unroll
            for (int nf = 0; nf < 4; nf++) {
                #pragma unroll
                for (int cc = 0; cc < 2; cc++) {
                    const int jj = j0 + wn * 32 + nf * 8 + (lane & 3) * 2 + cc;
                    const int ai = half * 2 + cc;
                    const float hr = acc[0][nf][ai] + bhh[jj];
                    const float hz = acc[1][nf][ai] + bhh[Hdim + jj];
                    const float hn = acc[2][nf][ai] + bhh[2 * Hdim + jj];
                    const float r = sigmoidf_(xrow[jj] + hr);
                    const float z = sigmoidf_(xrow[Hdim + jj] + hz);
                    const float n = tanhf(xrow[2 * Hdim + jj] + r * hn);
                    const float hold = __half2float(hhr[jj]) + __half2float(hlr[jj]);
                    const float hnew = gate * ((1.0f - z) * n + z * hold) + (1.0f - gate) * hold;
                    if (last) {
                        outp[bb * Hdim + jj] = hnew;
                    } else {
                        const __half hb = __float2half_rn(hnew);
                        hhiN[bb * Hdim + jj] = hb;
                        hloN[bb * Hdim + jj] = __float2half_rn(hnew - __half2float(hb));
                    }
                }
            }
        }

        if (!last) {
            __syncthreads();
            if (tid == 0) {
                __threadfence();
                const unsigned target = (unsigned)(s + 1);
                unsigned arr = atomicAdd(&g_bar_count, 1u);
                if (arr == 127u) {
                    g_bar_count = 0u;
                    __threadfence();
                    atomicExch(&g_bar_gen, target);
                } else {
                    unsigned v;
                    do {
                        asm volatile("ld.acquire.gpu.u32 %0, [%1];" : "=r"(v) : "l"(&g_bar_gen));
                    } while (v < target);
                }
            }
            __syncthreads();
        }
    }
}

// ---------------------------------------------------------------------------
extern "C" void kernel_launch(void* const* d_in, const int* in_sizes, int n_in,
                              void* d_out, int out_size)
{
    const float* C    = (const float*)d_in[0];
    const float* Q    = (const float*)d_in[1];
    const float* PM   = (const float*)d_in[2];
    const float* fc1w = (const float*)d_in[3];
    const float* fc1b = (const float*)d_in[4];
    const float* fc2w = (const float*)d_in[5];
    const float* fc2b = (const float*)d_in[6];
    const float* Wih  = (const float*)d_in[7];
    const float* Whh  = (const float*)d_in[8];
    const float* bih  = (const float*)d_in[9];
    const float* bhh  = (const float*)d_in[10];
    float* out = (float*)d_out;

    static int configured = 0;
    if (!configured) {
        cudaFuncSetAttribute(G_mma,    cudaFuncAttributeMaxDynamicSharedMemorySize, 2 * GST);
        cudaFuncSetAttribute(xg_mma,   cudaFuncAttributeMaxDynamicSharedMemorySize, 3 * XST);
        cudaFuncSetAttribute(gru_pers, cudaFuncAttributeMaxDynamicSharedMemorySize, GRU_SMEM);
        configured = 1;
    }

    zero_init_kernel<<<(Bdim*Hdim + 255)/256, 256>>>();
    split_C16_kernel<<<32768, 256>>>(C);
    cvt_W16_kernel<<<1792, 256>>>(Wih, Whh, fc1w);
    G_mma<<<Mrows/128, 256, 2 * GST>>>(C, Q, PM, fc1b, fc2w, fc2b);
    xg_mma<<<dim3(Mrows/128, H3/256), 512, 3 * XST>>>(bih);
    gru_pers<<<dim3(Bdim/64, Hdim/64), 256, GRU_SMEM>>>(bhh, out);
}

// round 7
// speedup vs baseline: 3.3050x; 1.1929x over previous
#include <cuda_runtime.h>
#include <cuda_fp16.h>
#include <math.h>
#include <stdint.h>

#define Hdim 512
#define SHdim 120
#define Bdim 1024
#define Sdim 64
#define H3 1536
#define H4 2048
#define Mrows (Bdim*Sdim)
#define LD 80          // 32-half (64B) rows + 16B pad
#define LD64 144       // 64-half (128B) rows + 16B pad
#define WLD 1040       // resident Whh rows: 512 halves (1024B) + 16B pad

// ----------------------------- device scratch ------------------------------
__device__ float g_G[Sdim*Bdim];
__device__ float g_xg[(size_t)Sdim*Bdim*H3];
__device__ float g_hf[2][Bdim*Hdim];                 // fp32 carried state
__device__ __half g_h16[2][Bdim*Hdim];               // fp16 MMA operand image
__device__ __half g_C16hi[(size_t)Mrows*Hdim];
__device__ __half g_C16lo[(size_t)Mrows*Hdim];
__device__ __half g_Wih16[H3*Hdim];
__device__ __half g_Whh16[H3*Hdim];
__device__ __half g_fc1w16[128*H4];
__device__ unsigned g_bar_count;
__device__ unsigned g_bar_gen;

__device__ __forceinline__ float sigmoidf_(float x){ return 1.0f/(1.0f+expf(-x)); }

// ----------------------------- asm helpers ---------------------------------
__device__ __forceinline__ uint32_t smem_u32(const void* p){
    uint32_t a;
    asm("{ .reg .u64 t; cvta.to.shared.u64 t, %1; cvt.u32.u64 %0, t; }" : "=r"(a) : "l"(p));
    return a;
}
__device__ __forceinline__ void mma16816(float* c, uint32_t a0, uint32_t a1,
                                         uint32_t a2, uint32_t a3,
                                         uint32_t b0, uint32_t b1){
    asm volatile(
        "mma.sync.aligned.m16n8k16.row.col.f32.f16.f16.f32 "
        "{%0,%1,%2,%3},{%4,%5,%6,%7},{%8,%9},{%0,%1,%2,%3};"
        : "+f"(c[0]), "+f"(c[1]), "+f"(c[2]), "+f"(c[3])
        : "r"(a0), "r"(a1), "r"(a2), "r"(a3), "r"(b0), "r"(b1));
}
#define LDSM4(r0,r1,r2,r3, addr) \
    asm volatile("ldmatrix.sync.aligned.m8n8.x4.shared.b16 {%0,%1,%2,%3}, [%4];" \
        : "=r"(r0), "=r"(r1), "=r"(r2), "=r"(r3) : "r"(addr))
#define STS16(dst, v) asm volatile("st.shared.v4.b32 [%0],{%1,%2,%3,%4};" \
        :: "r"(dst), "r"((v).x), "r"((v).y), "r"((v).z), "r"((v).w))
#define STS8(dst, x, y) asm volatile("st.shared.v2.b32 [%0],{%1,%2};" \
        :: "r"(dst), "r"(x), "r"(y))
#define CP16(dst, src) asm volatile("cp.async.cg.shared.global [%0], [%1], 16;" \
        :: "r"(dst), "l"(src))
#define CP_COMMIT() asm volatile("cp.async.commit_group;" ::: "memory")
#define CP_WAIT0()  asm volatile("cp.async.wait_group 0;" ::: "memory")
#define CP_WAIT1()  asm volatile("cp.async.wait_group 1;" ::: "memory")
#define CP_WAIT2()  asm volatile("cp.async.wait_group 2;" ::: "memory")

// ----------------------------- init / convert ------------------------------
__global__ void zero_init_kernel(){
    int i = blockIdx.x * blockDim.x + threadIdx.x;
    if (i < Bdim * Hdim) {
        g_hf[0][i] = 0.0f;
        g_h16[0][i] = __float2half_rn(0.0f);
    }
    if (i == 0) { g_bar_count = 0u; g_bar_gen = 0u; }
}
__device__ __forceinline__ void split4h(float4 v, uint2* hi, uint2* lo){
    __half2 h0(__float2half_rn(v.x), __float2half_rn(v.y));
    __half2 h1(__float2half_rn(v.z), __float2half_rn(v.w));
    __half2 l0(__float2half_rn(v.x - __half2float(h0.x)),
               __float2half_rn(v.y - __half2float(h0.y)));
    __half2 l1(__float2half_rn(v.z - __half2float(h1.x)),
               __float2half_rn(v.w - __half2float(h1.y)));
    hi->x = *(uint32_t*)&h0; hi->y = *(uint32_t*)&h1;
    lo->x = *(uint32_t*)&l0; lo->y = *(uint32_t*)&l1;
}
__global__ void split_C16_kernel(const float* __restrict__ src){
    size_t i = (size_t)blockIdx.x * blockDim.x + threadIdx.x;   // 8388608 float4
    uint2 h, l;
    split4h(((const float4*)src)[i], &h, &l);
    ((uint2*)g_C16hi)[i] = h;
    ((uint2*)g_C16lo)[i] = l;
}
__device__ __forceinline__ uint2 cvt4h(float4 v){
    __half2 h0(__float2half_rn(v.x), __float2half_rn(v.y));
    __half2 h1(__float2half_rn(v.z), __float2half_rn(v.w));
    uint2 o; o.x = *(uint32_t*)&h0; o.y = *(uint32_t*)&h1; return o;
}
__global__ void cvt_W16_kernel(const float* __restrict__ wih,
                               const float* __restrict__ whh,
                               const float* __restrict__ fc1w){
    int i = blockIdx.x * blockDim.x + threadIdx.x;
    const int nW = H3 * Hdim / 4;                    // 196608
    const int nF = SHdim * H4 / 4;                   // 61440
    if (i < nW) {
        ((uint2*)g_Wih16)[i] = cvt4h(((const float4*)wih)[i]);
    } else if (i < 2*nW) {
        int j = i - nW;
        ((uint2*)g_Whh16)[j] = cvt4h(((const float4*)whh)[j]);
    } else if (i < 2*nW + nF) {
        int j = i - 2*nW;
        ((uint2*)g_fc1w16)[j] = cvt4h(((const float4*)fc1w)[j]);
    } else {
        int j = i - 2*nW - nF;                       // 4096 pad uint2
        ((uint2*)g_fc1w16)[nF + j] = make_uint2(0u, 0u);
    }
}

// ---------------------------------------------------------------------------
// Gate network: feat fp16(hi) @ fc1w16^T; Q/PM cached in static smem.
// CTA m-tile 128, n 128 (120 real), 256 threads; 64 chunks of k32.
// ---------------------------------------------------------------------------
#define GA2 (128*LD)               // 10240
#define GST (2*GA2)                // stage = A + B = 20480

__global__ __launch_bounds__(256, 1) void G_mma(
    const float* __restrict__ C, const float* __restrict__ Q,
    const float* __restrict__ PM,
    const float* __restrict__ fc1b, const float* __restrict__ fc2w,
    const float* __restrict__ fc2b)
{
    extern __shared__ __align__(16) char smg2[];
    __shared__ __align__(16) float sQP[2][2][Hdim];   // [q/pm][b_local][k]
    const uint32_t sb = smem_u32(smg2);
    const int tid = threadIdx.x, lane = tid & 31, wm = tid >> 5;
    const int m0 = blockIdx.x * 128;

    // cache Q / PM rows for the 2 batch indices this CTA touches
    {
        const int b_base = m0 >> 6;                   // 2 consecutive b
        for (int q = tid; q < 2 * Hdim / 4; q += 256) {
            const int bl = q / (Hdim/4), u = q % (Hdim/4);
            *(float4*)&sQP[0][bl][u*4] = *(const float4*)(Q  + (size_t)(b_base+bl)*Hdim + u*4);
            *(float4*)&sQP[1][bl][u*4] = *(const float4*)(PM + (size_t)(b_base+bl)*Hdim + u*4);
        }
    }
    __syncthreads();

    float acc[16][4];
    #pragma unroll
    for (int a = 0; a < 16; a++)
        #pragma unroll
        for (int d = 0; d < 4; d++) acc[a][d] = 0.0f;

    // chunk helpers (inline)
    auto G_fetch = [&](int c, float4* rc) {
        const int base0 = (c & 15) * 32;
        #pragma unroll
        for (int i = 0; i < 4; i++) {
            const int q = tid + i * 256;
            const int r = q >> 3, u = q & 7;
            rc[i] = *(const float4*)(C + (size_t)(m0 + r) * Hdim + base0 + u * 4);
        }
    };
    auto G_store = [&](int c, uint32_t buf, const float4* rc) {
        const int part = c >> 4;
        const int base0 = (c & 15) * 32;
        const int sel = (part == 0 || part == 2) ? 0 : 1;
        #pragma unroll
        for (int i = 0; i < 4; i++) {
            const int q = tid + i * 256;
            const int r = q >> 3, u = q & 7;
            const float4 c4 = rc[i];
            const float4 v4 = *(const float4*)&sQP[sel][r >> 6][base0 + u * 4];
            float4 f;
            if (part < 2) { f.x=c4.x*v4.x; f.y=c4.y*v4.y; f.z=c4.z*v4.z; f.w=c4.w*v4.w; }
            else { f.x=fabsf(c4.x-v4.x); f.y=fabsf(c4.y-v4.y); f.z=fabsf(c4.z-v4.z); f.w=fabsf(c4.w-v4.w); }
            uint2 h = cvt4h(f);
            STS8(buf + r * LD + u * 8, h.x, h.y);
        }
    };
    auto G_cpB = [&](int c, uint32_t buf) {
        const int part = c >> 4;
        const int base0 = (c & 15) * 32;
        #pragma unroll
        for (int i = 0; i < 2; i++) {
            const int q = tid + i * 256;
            const int r = q >> 2, u = q & 3;
            CP16(buf + GA2 + r * LD + u * 16,
                 g_fc1w16 + (size_t)r * H4 + part * 512 + base0 + u * 8);
        }
    };

    float4 rc[4];
    G_fetch(0, rc);
    G_cpB(0, sb);
    CP_COMMIT();
    G_store(0, sb, rc);
    CP_WAIT0();
    __syncthreads();

    const uint32_t a_lrow = (wm * 16 + (lane & 15)) * LD + (lane >> 4) * 16;
    const uint32_t b_lrow = ((lane >> 4) * 8 + (lane & 7)) * LD + ((lane >> 3) & 1) * 16;

    for (int c = 0; c < 64; c++) {
        const uint32_t cur = sb + (c & 1) * GST;
        const uint32_t nxt = sb + ((c + 1) & 1) * GST;
        if (c < 63) {
            G_fetch(c + 1, rc);
            G_cpB(c + 1, nxt);
        }
        CP_COMMIT();
        #pragma unroll
        for (int kk = 0; kk < 2; kk++) {
            uint32_t b[8][4];
            #pragma unroll
            for (int nb = 0; nb < 8; nb++)
                LDSM4(b[nb][0], b[nb][1], b[nb][2], b[nb][3],
                      cur + GA2 + (nb * 16) * LD + kk * 32 + b_lrow);
            uint32_t a0, a1, a2, a3;
            LDSM4(a0, a1, a2, a3, cur + a_lrow + kk * 32);
            #pragma unroll
            for (int nb = 0; nb < 8; nb++) {
                mma16816(acc[nb*2],   a0, a1, a2, a3, b[nb][0], b[nb][1]);
                mma16816(acc[nb*2+1], a0, a1, a2, a3, b[nb][2], b[nb][3]);
            }
        }
        if (c < 63) G_store(c + 1, nxt, rc);
        CP_WAIT0();
        __syncthreads();
    }

    const float fc2b0 = fc2b[0];
    #pragma unroll
    for (int half = 0; half < 2; half++) {
        float partial = 0.0f;
        #pragma unroll
        for (int nb = 0; nb < 16; nb++) {
            #pragma unroll
            for (int cc = 0; cc < 2; cc++) {
                const int n = nb * 8 + (lane & 3) * 2 + cc;
                if (n < SHdim)
                    partial += fc2w[n] * tanhf(acc[nb][half*2+cc] + fc1b[n]);
            }
        }
        partial += __shfl_xor_sync(0xffffffffu, partial, 1);
        partial += __shfl_xor_sync(0xffffffffu, partial, 2);
        if ((lane & 3) == 0) {
            const int m = m0 + wm * 16 + (lane >> 2) + half * 8;
            g_G[(m & 63) * Bdim + (m >> 6)] = sigmoidf_(partial + fc2b0);
        }
    }
}

// ---------------------------------------------------------------------------
// xg = C @ Wih^T + b. CTA 128m x 256n, 512 threads, cp.async 4-stage, k64.
// 16 chunks: c<8 hi (k0=c*64), c>=8 lo.
// ---------------------------------------------------------------------------
#define XA2 (128*LD64)             // 18432
#define XST (XA2 + 256*LD64)       // 55296

__device__ __forceinline__ void xg_ld(uint32_t buf, int tid, int m0, int n0, int c){
    const __half* __restrict__ Asrc = (c < 8) ? g_C16hi : g_C16lo;
    const int k0 = (c & 7) * 64;
    #pragma unroll
    for (int i = 0; i < 2; i++) {            // A: 1024 u4
        const int q = tid + i * 512;
        const int r = q >> 3, u = q & 7;
        CP16(buf + r * LD64 + u * 16, Asrc + (size_t)(m0 + r) * Hdim + k0 + u * 8);
    }
    #pragma unroll
    for (int i = 0; i < 4; i++) {            // B: 2048 u4
        const int q = tid + i * 512;
        const int r = q >> 3, u = q & 7;
        CP16(buf + XA2 + r * LD64 + u * 16, g_Wih16 + (size_t)(n0 + r) * Hdim + k0 + u * 8);
    }
}

__global__ __launch_bounds__(512, 1) void xg_mma(const float* __restrict__ bih)
{
    extern __shared__ __align__(16) char smx[];
    const uint32_t sb = smem_u32(smx);
    const int tid = threadIdx.x, lane = tid & 31, wid = tid >> 5;
    const int wm = wid >> 3, wn = wid & 7;
    const int m0 = blockIdx.x * 128, n0 = blockIdx.y * 256;

    float acc[4][4][4];
    #pragma unroll
    for (int a = 0; a < 4; a++)
        #pragma unroll
        for (int b = 0; b < 4; b++)
            #pragma unroll
            for (int d = 0; d < 4; d++) acc[a][b][d] = 0.0f;

    xg_ld(sb, tid, m0, n0, 0); CP_COMMIT();
    xg_ld(sb + XST, tid, m0, n0, 1); CP_COMMIT();
    xg_ld(sb + 2*XST, tid, m0, n0, 2); CP_COMMIT();

    const uint32_t a_lrow = (lane & 15) * LD64 + (lane >> 4) * 16;
    const uint32_t b_lrow = ((lane >> 4) * 8 + (lane & 7)) * LD64 + ((lane >> 3) & 1) * 16;

    for (int c = 0; c < 16; c++) {
        CP_WAIT2();
        __syncthreads();
        if (c + 3 < 16) xg_ld(sb + ((c + 3) & 3) * XST, tid, m0, n0, c + 3);
        CP_COMMIT();
        const uint32_t cur = sb + (c & 3) * XST;
        #pragma unroll
        for (int kk = 0; kk < 4; kk++) {
            uint32_t a[4][4];
            #pragma unroll
            for (int mf = 0; mf < 4; mf++)
                LDSM4(a[mf][0], a[mf][1], a[mf][2], a[mf][3],
                      cur + (wm * 64 + mf * 16) * LD64 + kk * 32 + a_lrow);
            #pragma unroll
            for (int nfp = 0; nfp < 2; nfp++) {
                uint32_t b0, b1, b2, b3;
                LDSM4(b0, b1, b2, b3,
                      cur + XA2 + (wn * 32 + nfp * 16) * LD64 + kk * 32 + b_lrow);
                #pragma unroll
                for (int mf = 0; mf < 4; mf++) {
                    mma16816(acc[mf][nfp*2],   a[mf][0], a[mf][1], a[mf][2], a[mf][3], b0, b1);
                    mma16816(acc[mf][nfp*2+1], a[mf][0], a[mf][1], a[mf][2], a[mf][3], b2, b3);
                }
            }
        }
    }

    #pragma unroll
    for (int mf = 0; mf < 4; mf++) {
        #pragma unroll
        for (int half = 0; half < 2; half++) {
            const int m = m0 + wm * 64 + mf * 16 + (lane >> 2) + half * 8;
            const size_t ob = ((size_t)(m & 63) * Bdim + (m >> 6)) * H3;
            #pragma unroll
            for (int nf = 0; nf < 4; nf++) {
                const int jj = n0 + wn * 32 + nf * 8 + (lane & 3) * 2;
                float2 o;
                o.x = acc[mf][nf][half*2+0] + bih[jj];
                o.y = acc[mf][nf][half*2+1] + bih[jj+1];
                *(float2*)(g_xg + ob + jj) = o;
            }
        }
    }
}

// ---------------------------------------------------------------------------
// Persistent GRU: Whh resident, h fp16 single-term (fp32 carried state),
// 8 chunks k64 per step, 3-stage cp.async.
// ---------------------------------------------------------------------------
#define WB_SZ (192*WLD)            // 199680
#define GAST (64*LD64)             // 9216/stage, 3 stages
#define GRU_SMEM (WB_SZ + 3*GAST)  // 227328

__device__ __forceinline__ void gru_ldA(uint32_t dst, int tid, int b0, int c,
                                        const __half* __restrict__ h16){
    const int k0 = c * 64;
    #pragma unroll
    for (int i = 0; i < 2; i++) {            // 512 u4
        const int q = tid + i * 256;
        const int r = q >> 3, u = q & 7;
        CP16(dst + r * LD64 + u * 16, h16 + (size_t)(b0 + r) * Hdim + k0 + u * 8);
    }
}

__global__ __launch_bounds__(256, 1) void gru_pers(
    const float* __restrict__ bhh, float* __restrict__ outp)
{
    extern __shared__ __align__(16) char smp[];
    const uint32_t sb = smem_u32(smp);
    const uint32_t WB = sb;
    const uint32_t AB = sb + WB_SZ;
    const int tid = threadIdx.x, lane = tid & 31, wid = tid >> 5;
    const int wm = wid >> 1, wn = wid & 1;
    const int b0 = blockIdx.x * 64, j0 = blockIdx.y * 64;

    // resident Whh: 192 rows x 512 halves
    for (int q = tid; q < 12288; q += 256) {
        const int r = q >> 6, u = q & 63;
        const int g = r >> 6, jj = r & 63;
        uint4 v = *(const uint4*)(g_Whh16 + (size_t)((g << 9) + j0 + jj) * Hdim + u * 8);
        STS16(WB + r * WLD + u * 16, v);
    }
    __syncthreads();

    const uint32_t a_lrow = (wm * 16 + (lane & 15)) * LD64 + (lane >> 4) * 16;
    const uint32_t b_lrowW = ((lane >> 4) * 8 + (lane & 7)) * WLD + ((lane >> 3) & 1) * 16;

    for (int s = 0; s < Sdim; s++) {
        const int par = s & 1;
        const __half* __restrict__ h16 = g_h16[par];

        float acc[3][4][4];
        #pragma unroll
        for (int g = 0; g < 3; g++)
            #pragma unroll
            for (int b = 0; b < 4; b++)
                #pragma unroll
                for (int d = 0; d < 4; d++) acc[g][b][d] = 0.0f;

        gru_ldA(AB, tid, b0, 0, h16); CP_COMMIT();
        gru_ldA(AB + GAST, tid, b0, 1, h16); CP_COMMIT();

        for (int c = 0; c < 8; c++) {
            CP_WAIT1();
            __syncthreads();
            if (c + 2 < 8) gru_ldA(AB + ((c + 2) % 3) * GAST, tid, b0, c + 2, h16);
            CP_COMMIT();
            const uint32_t cur = AB + (c % 3) * GAST;
            const uint32_t koff = c * 128;
            #pragma unroll
            for (int kk = 0; kk < 4; kk++) {
                uint32_t a0, a1, a2, a3;
                LDSM4(a0, a1, a2, a3, cur + a_lrow + kk * 32);
                #pragma unroll
                for (int g = 0; g < 3; g++) {
                    #pragma unroll
                    for (int nfp = 0; nfp < 2; nfp++) {
                        uint32_t b0r, b1r, b2r, b3r;
                        LDSM4(b0r, b1r, b2r, b3r,
                              WB + (g * 64 + wn * 32 + nfp * 16) * WLD + koff + kk * 32 + b_lrowW);
                        mma16816(acc[g][nfp*2],   a0, a1, a2, a3, b0r, b1r);
                        mma16816(acc[g][nfp*2+1], a0, a1, a2, a3, b2r, b3r);
                    }
                }
            }
        }

        // epilogue: fp32 carried h
        const float* __restrict__ xg_s = g_xg + (size_t)s * Bdim * H3;
        const int last = (s == Sdim - 1);
        const float* __restrict__ hf_in = g_hf[par];
        float* __restrict__ hf_out = g_hf[par ^ 1];
        __half* __restrict__ h16N = g_h16[par ^ 1];

        #pragma unroll
        for (int half = 0; half < 2; half++) {
            const int bb = b0 + wm * 16 + (lane >> 2) + half * 8;
            const float gate = g_G[s * Bdim + bb];
            const float* __restrict__ xrow = xg_s + (size_t)bb * H3;
            const float* __restrict__ hrow = hf_in + bb * Hdim;
            #pragma unroll
            for (int nf = 0; nf < 4; nf++) {
                #pragma unroll
                for (int cc = 0; cc < 2; cc++) {
                    const int jj = j0 + wn * 32 + nf * 8 + (lane & 3) * 2 + cc;
                    const int ai = half * 2 + cc;
                    const float hr = acc[0][nf][ai] + bhh[jj];
                    const float hz = acc[1][nf][ai] + bhh[Hdim + jj];
                    const float hn = acc[2][nf][ai] + bhh[2 * Hdim + jj];
                    const float r = sigmoidf_(xrow[jj] + hr);
                    const float z = sigmoidf_(xrow[Hdim + jj] + hz);
                    const float n = tanhf(xrow[2 * Hdim + jj] + r * hn);
                    const float hold = hrow[jj];
                    const float hnew = gate * ((1.0f - z) * n + z * hold) + (1.0f - gate) * hold;
                    if (last) {
                        outp[bb * Hdim + jj] = hnew;
                    } else {
                        hf_out[bb * Hdim + jj] = hnew;
                        h16N[bb * Hdim + jj] = __float2half_rn(hnew);
                    }
                }
            }
        }

        if (!last) {
            __syncthreads();
            if (tid == 0) {
                __threadfence();
                const unsigned target = (unsigned)(s + 1);
                unsigned arr = atomicAdd(&g_bar_count, 1u);
                if (arr == 127u) {
                    g_bar_count = 0u;
                    __threadfence();
                    atomicExch(&g_bar_gen, target);
                } else {
                    unsigned v;
                    do {
                        asm volatile("ld.acquire.gpu.u32 %0, [%1];" : "=r"(v) : "l"(&g_bar_gen));
                    } while (v < target);
                }
            }
            __syncthreads();
        }
    }
}

// ---------------------------------------------------------------------------
extern "C" void kernel_launch(void* const* d_in, const int* in_sizes, int n_in,
                              void* d_out, int out_size)
{
    const float* C    = (const float*)d_in[0];
    const float* Q    = (const float*)d_in[1];
    const float* PM   = (const float*)d_in[2];
    const float* fc1w = (const float*)d_in[3];
    const float* fc1b = (const float*)d_in[4];
    const float* fc2w = (const float*)d_in[5];
    const float* fc2b = (const float*)d_in[6];
    const float* Wih  = (const float*)d_in[7];
    const float* Whh  = (const float*)d_in[8];
    const float* bih  = (const float*)d_in[9];
    const float* bhh  = (const float*)d_in[10];
    float* out = (float*)d_out;

    static int configured = 0;
    if (!configured) {
        cudaFuncSetAttribute(G_mma,    cudaFuncAttributeMaxDynamicSharedMemorySize, 2 * GST);
        cudaFuncSetAttribute(xg_mma,   cudaFuncAttributeMaxDynamicSharedMemorySize, 4 * XST);
        cudaFuncSetAttribute(gru_pers, cudaFuncAttributeMaxDynamicSharedMemorySize, GRU_SMEM);
        configured = 1;
    }

    zero_init_kernel<<<(Bdim*Hdim + 255)/256, 256>>>();
    split_C16_kernel<<<32768, 256>>>(C);
    cvt_W16_kernel<<<1792, 256>>>(Wih, Whh, fc1w);
    G_mma<<<Mrows/128, 256, 2 * GST>>>(C, Q, PM, fc1b, fc2w, fc2b);
    xg_mma<<<dim3(Mrows/128, H3/256), 512, 4 * XST>>>(bih);
    gru_pers<<<dim3(Bdim/64, Hdim/64), 256, GRU_SMEM>>>(bhh, out);
}

// round 8
// speedup vs baseline: 5.5981x; 1.6938x over previous
#include <cuda_runtime.h>
#include <cuda_fp16.h>
#include <math.h>
#include <stdint.h>

#define Hdim 512
#define SHdim 120
#define Bdim 1024
#define Sdim 64
#define H3 1536
#define H4 2048
#define Mrows (Bdim*Sdim)
#define LD 80          // 32-half (64B) rows + 16B pad
#define LD64 144       // 64-half (128B) rows + 16B pad
#define WLD 1040       // resident Whh rows: 512 halves (1024B) + 16B pad

// ----------------------------- device scratch ------------------------------
__device__ float g_G[Sdim*Bdim];
__device__ __half g_xg16[(size_t)Sdim*Bdim*H3];      // xg in fp16
__device__ __half g_h16[2][Bdim*Hdim];               // fp16 MMA operand image
__device__ __half g_C16[(size_t)Mrows*Hdim];         // C fp16 (hi only)
__device__ __half g_Wih16[H3*Hdim];
__device__ __half g_Whh16[H3*Hdim];
__device__ __half g_fc1w16[128*H4];
__device__ unsigned g_bar_count;
__device__ unsigned g_bar_gen;

__device__ __forceinline__ float sigmoidf_(float x){ return 1.0f/(1.0f+expf(-x)); }

// ----------------------------- asm helpers ---------------------------------
__device__ __forceinline__ uint32_t smem_u32(const void* p){
    uint32_t a;
    asm("{ .reg .u64 t; cvta.to.shared.u64 t, %1; cvt.u32.u64 %0, t; }" : "=r"(a) : "l"(p));
    return a;
}
__device__ __forceinline__ void mma16816(float* c, uint32_t a0, uint32_t a1,
                                         uint32_t a2, uint32_t a3,
                                         uint32_t b0, uint32_t b1){
    asm volatile(
        "mma.sync.aligned.m16n8k16.row.col.f32.f16.f16.f32 "
        "{%0,%1,%2,%3},{%4,%5,%6,%7},{%8,%9},{%0,%1,%2,%3};"
        : "+f"(c[0]), "+f"(c[1]), "+f"(c[2]), "+f"(c[3])
        : "r"(a0), "r"(a1), "r"(a2), "r"(a3), "r"(b0), "r"(b1));
}
#define LDSM4(r0,r1,r2,r3, addr) \
    asm volatile("ldmatrix.sync.aligned.m8n8.x4.shared.b16 {%0,%1,%2,%3}, [%4];" \
        : "=r"(r0), "=r"(r1), "=r"(r2), "=r"(r3) : "r"(addr))
#define STS16(dst, v) asm volatile("st.shared.v4.b32 [%0],{%1,%2,%3,%4};" \
        :: "r"(dst), "r"((v).x), "r"((v).y), "r"((v).z), "r"((v).w))
#define STS8(dst, x, y) asm volatile("st.shared.v2.b32 [%0],{%1,%2};" \
        :: "r"(dst), "r"(x), "r"(y))
#define CP16(dst, src) asm volatile("cp.async.cg.shared.global [%0], [%1], 16;" \
        :: "r"(dst), "l"(src))
#define CP_COMMIT() asm volatile("cp.async.commit_group;" ::: "memory")
#define CP_WAIT0()  asm volatile("cp.async.wait_group 0;" ::: "memory")
#define CP_WAIT1()  asm volatile("cp.async.wait_group 1;" ::: "memory")
#define CP_WAIT2()  asm volatile("cp.async.wait_group 2;" ::: "memory")

// ----------------------------- init / convert ------------------------------
__global__ void zero_init_kernel(){
    int i = blockIdx.x * blockDim.x + threadIdx.x;
    if (i < Bdim * Hdim) g_h16[0][i] = __float2half_rn(0.0f);
    if (i == 0) { g_bar_count = 0u; g_bar_gen = 0u; }
}
__device__ __forceinline__ uint2 cvt4h(float4 v){
    __half2 h0(__float2half_rn(v.x), __float2half_rn(v.y));
    __half2 h1(__float2half_rn(v.z), __float2half_rn(v.w));
    uint2 o; o.x = *(uint32_t*)&h0; o.y = *(uint32_t*)&h1; return o;
}
__global__ void cvt_C16_kernel(const float* __restrict__ src){
    size_t i = (size_t)blockIdx.x * blockDim.x + threadIdx.x;   // 8388608 float4
    ((uint2*)g_C16)[i] = cvt4h(((const float4*)src)[i]);
}
__global__ void cvt_W16_kernel(const float* __restrict__ wih,
                               const float* __restrict__ whh,
                               const float* __restrict__ fc1w){
    int i = blockIdx.x * blockDim.x + threadIdx.x;
    const int nW = H3 * Hdim / 4;                    // 196608
    const int nF = SHdim * H4 / 4;                   // 61440
    if (i < nW) {
        ((uint2*)g_Wih16)[i] = cvt4h(((const float4*)wih)[i]);
    } else if (i < 2*nW) {
        int j = i - nW;
        ((uint2*)g_Whh16)[j] = cvt4h(((const float4*)whh)[j]);
    } else if (i < 2*nW + nF) {
        int j = i - 2*nW;
        ((uint2*)g_fc1w16)[j] = cvt4h(((const float4*)fc1w)[j]);
    } else {
        int j = i - 2*nW - nF;                       // 4096 pad uint2
        ((uint2*)g_fc1w16)[nF + j] = make_uint2(0u, 0u);
    }
}

// ---------------------------------------------------------------------------
// Gate network: feat fp16 @ fc1w16^T; 2-chunk-ahead LDG prefetch.
// CTA m-tile 128, n 128 (120 real), 256 threads; 64 chunks of k32.
// ---------------------------------------------------------------------------
#define GA2 (128*LD)               // 10240
#define GST (2*GA2)                // stage = A + B = 20480

__global__ __launch_bounds__(256, 1) void G_mma(
    const float* __restrict__ C, const float* __restrict__ Q,
    const float* __restrict__ PM,
    const float* __restrict__ fc1b, const float* __restrict__ fc2w,
    const float* __restrict__ fc2b)
{
    extern __shared__ __align__(16) char smg2[];
    __shared__ __align__(16) float sQP[2][2][Hdim];   // [q/pm][b_local][k]
    const uint32_t sb = smem_u32(smg2);
    const int tid = threadIdx.x, lane = tid & 31, wm = tid >> 5;
    const int m0 = blockIdx.x * 128;

    {
        const int b_base = m0 >> 6;
        for (int q = tid; q < 2 * Hdim / 4; q += 256) {
            const int bl = q / (Hdim/4), u = q % (Hdim/4);
            *(float4*)&sQP[0][bl][u*4] = *(const float4*)(Q  + (size_t)(b_base+bl)*Hdim + u*4);
            *(float4*)&sQP[1][bl][u*4] = *(const float4*)(PM + (size_t)(b_base+bl)*Hdim + u*4);
        }
    }
    __syncthreads();

    float acc[16][4];
    #pragma unroll
    for (int a = 0; a < 16; a++)
        #pragma unroll
        for (int d = 0; d < 4; d++) acc[a][d] = 0.0f;

    auto G_fetch = [&](int c, float4* rc) {
        const int base0 = (c & 15) * 32;
        #pragma unroll
        for (int i = 0; i < 4; i++) {
            const int q = tid + i * 256;
            const int r = q >> 3, u = q & 7;
            rc[i] = *(const float4*)(C + (size_t)(m0 + r) * Hdim + base0 + u * 4);
        }
    };
    auto G_store = [&](int c, uint32_t buf, const float4* rc) {
        const int part = c >> 4;
        const int base0 = (c & 15) * 32;
        const int sel = (part == 0 || part == 2) ? 0 : 1;
        #pragma unroll
        for (int i = 0; i < 4; i++) {
            const int q = tid + i * 256;
            const int r = q >> 3, u = q & 7;
            const float4 c4 = rc[i];
            const float4 v4 = *(const float4*)&sQP[sel][r >> 6][base0 + u * 4];
            float4 f;
            if (part < 2) { f.x=c4.x*v4.x; f.y=c4.y*v4.y; f.z=c4.z*v4.z; f.w=c4.w*v4.w; }
            else { f.x=fabsf(c4.x-v4.x); f.y=fabsf(c4.y-v4.y); f.z=fabsf(c4.z-v4.z); f.w=fabsf(c4.w-v4.w); }
            uint2 h = cvt4h(f);
            STS8(buf + r * LD + u * 8, h.x, h.y);
        }
    };
    auto G_cpB = [&](int c, uint32_t buf) {
        const int part = c >> 4;
        const int base0 = (c & 15) * 32;
        #pragma unroll
        for (int i = 0; i < 2; i++) {
            const int q = tid + i * 256;
            const int r = q >> 2, u = q & 3;
            CP16(buf + GA2 + r * LD + u * 16,
                 g_fc1w16 + (size_t)r * H4 + part * 512 + base0 + u * 8);
        }
    };

    float4 rc[2][4];
    G_fetch(0, rc[0]);
    G_cpB(0, sb);
    CP_COMMIT();
    G_store(0, sb, rc[0]);
    G_fetch(1, rc[1]);               // chunk 1 fetched early (2-ahead steady state)
    CP_WAIT0();
    __syncthreads();

    const uint32_t a_lrow = (wm * 16 + (lane & 15)) * LD + (lane >> 4) * 16;
    const uint32_t b_lrow = ((lane >> 4) * 8 + (lane & 7)) * LD + ((lane >> 3) & 1) * 16;

    for (int c = 0; c < 64; c++) {
        const uint32_t cur = sb + (c & 1) * GST;
        const uint32_t nxt = sb + ((c + 1) & 1) * GST;
        if (c + 2 < 64) G_fetch(c + 2, rc[c & 1]);
        if (c + 1 < 64) G_cpB(c + 1, nxt);
        CP_COMMIT();
        #pragma unroll
        for (int kk = 0; kk < 2; kk++) {
            uint32_t b[8][4];
            #pragma unroll
            for (int nb = 0; nb < 8; nb++)
                LDSM4(b[nb][0], b[nb][1], b[nb][2], b[nb][3],
                      cur + GA2 + (nb * 16) * LD + kk * 32 + b_lrow);
            uint32_t a0, a1, a2, a3;
            LDSM4(a0, a1, a2, a3, cur + a_lrow + kk * 32);
            #pragma unroll
            for (int nb = 0; nb < 8; nb++) {
                mma16816(acc[nb*2],   a0, a1, a2, a3, b[nb][0], b[nb][1]);
                mma16816(acc[nb*2+1], a0, a1, a2, a3, b[nb][2], b[nb][3]);
            }
        }
        if (c + 1 < 64) G_store(c + 1, nxt, rc[(c + 1) & 1]);
        CP_WAIT0();
        __syncthreads();
    }

    const float fc2b0 = fc2b[0];
    #pragma unroll
    for (int half = 0; half < 2; half++) {
        float partial = 0.0f;
        #pragma unroll
        for (int nb = 0; nb < 16; nb++) {
            #pragma unroll
            for (int cc = 0; cc < 2; cc++) {
                const int n = nb * 8 + (lane & 3) * 2 + cc;
                if (n < SHdim)
                    partial += fc2w[n] * tanhf(acc[nb][half*2+cc] + fc1b[n]);
            }
        }
        partial += __shfl_xor_sync(0xffffffffu, partial, 1);
        partial += __shfl_xor_sync(0xffffffffu, partial, 2);
        if ((lane & 3) == 0) {
            const int m = m0 + wm * 16 + (lane >> 2) + half * 8;
            g_G[(m & 63) * Bdim + (m >> 6)] = sigmoidf_(partial + fc2b0);
        }
    }
}

// ---------------------------------------------------------------------------
// xg = C @ Wih^T + b (fp16 A, single term). CTA 128m x 256n, 512 threads,
// cp.async 4-stage, 8 chunks of k64. Output fp16.
// ---------------------------------------------------------------------------
#define XA2 (128*LD64)             // 18432
#define XST (XA2 + 256*LD64)       // 55296

__device__ __forceinline__ void xg_ld(uint32_t buf, int tid, int m0, int n0, int c){
    const int k0 = c * 64;
    #pragma unroll
    for (int i = 0; i < 2; i++) {            // A: 1024 u4
        const int q = tid + i * 512;
        const int r = q >> 3, u = q & 7;
        CP16(buf + r * LD64 + u * 16, g_C16 + (size_t)(m0 + r) * Hdim + k0 + u * 8);
    }
    #pragma unroll
    for (int i = 0; i < 4; i++) {            // B: 2048 u4
        const int q = tid + i * 512;
        const int r = q >> 3, u = q & 7;
        CP16(buf + XA2 + r * LD64 + u * 16, g_Wih16 + (size_t)(n0 + r) * Hdim + k0 + u * 8);
    }
}

__global__ __launch_bounds__(512, 1) void xg_mma(const float* __restrict__ bih)
{
    extern __shared__ __align__(16) char smx[];
    const uint32_t sb = smem_u32(smx);
    const int tid = threadIdx.x, lane = tid & 31, wid = tid >> 5;
    const int wm = wid >> 3, wn = wid & 7;
    const int m0 = blockIdx.x * 128, n0 = blockIdx.y * 256;

    float acc[4][4][4];
    #pragma unroll
    for (int a = 0; a < 4; a++)
        #pragma unroll
        for (int b = 0; b < 4; b++)
            #pragma unroll
            for (int d = 0; d < 4; d++) acc[a][b][d] = 0.0f;

    xg_ld(sb, tid, m0, n0, 0); CP_COMMIT();
    xg_ld(sb + XST, tid, m0, n0, 1); CP_COMMIT();
    xg_ld(sb + 2*XST, tid, m0, n0, 2); CP_COMMIT();

    const uint32_t a_lrow = (lane & 15) * LD64 + (lane >> 4) * 16;
    const uint32_t b_lrow = ((lane >> 4) * 8 + (lane & 7)) * LD64 + ((lane >> 3) & 1) * 16;

    for (int c = 0; c < 8; c++) {
        CP_WAIT2();
        __syncthreads();
        if (c + 3 < 8) xg_ld(sb + ((c + 3) & 3) * XST, tid, m0, n0, c + 3);
        CP_COMMIT();
        const uint32_t cur = sb + (c & 3) * XST;
        #pragma unroll
        for (int kk = 0; kk < 4; kk++) {
            uint32_t a[4][4];
            #pragma unroll
            for (int mf = 0; mf < 4; mf++)
                LDSM4(a[mf][0], a[mf][1], a[mf][2], a[mf][3],
                      cur + (wm * 64 + mf * 16) * LD64 + kk * 32 + a_lrow);
            #pragma unroll
            for (int nfp = 0; nfp < 2; nfp++) {
                uint32_t b0, b1, b2, b3;
                LDSM4(b0, b1, b2, b3,
                      cur + XA2 + (wn * 32 + nfp * 16) * LD64 + kk * 32 + b_lrow);
                #pragma unroll
                for (int mf = 0; mf < 4; mf++) {
                    mma16816(acc[mf][nfp*2],   a[mf][0], a[mf][1], a[mf][2], a[mf][3], b0, b1);
                    mma16816(acc[mf][nfp*2+1], a[mf][0], a[mf][1], a[mf][2], a[mf][3], b2, b3);
                }
            }
        }
    }

    #pragma unroll
    for (int mf = 0; mf < 4; mf++) {
        #pragma unroll
        for (int half = 0; half < 2; half++) {
            const int m = m0 + wm * 64 + mf * 16 + (lane >> 2) + half * 8;
            const size_t ob = ((size_t)(m & 63) * Bdim + (m >> 6)) * H3;
            #pragma unroll
            for (int nf = 0; nf < 4; nf++) {
                const int jj = n0 + wn * 32 + nf * 8 + (lane & 3) * 2;
                const float ox = acc[mf][nf][half*2+0] + bih[jj];
                const float oy = acc[mf][nf][half*2+1] + bih[jj+1];
                *(__half2*)(g_xg16 + ob + jj) = __floats2half2_rn(ox, oy);
            }
        }
    }
}

// ---------------------------------------------------------------------------
// Persistent GRU: Whh resident; h state carried in REGISTERS (fp32), only the
// fp16 MMA image round-trips global. xg/gate prefetched at step top.
// ---------------------------------------------------------------------------
#define WB_SZ (192*WLD)            // 199680
#define GAST (64*LD64)             // 9216/stage, 3 stages
#define GRU_SMEM (WB_SZ + 3*GAST)  // 227328

__device__ __forceinline__ void gru_ldA(uint32_t dst, int tid, int b0, int c,
                                        const __half* __restrict__ h16){
    const int k0 = c * 64;
    #pragma unroll
    for (int i = 0; i < 2; i++) {            // 512 u4
        const int q = tid + i * 256;
        const int r = q >> 3, u = q & 7;
        CP16(dst + r * LD64 + u * 16, h16 + (size_t)(b0 + r) * Hdim + k0 + u * 8);
    }
}

__global__ __launch_bounds__(256, 1) void gru_pers(
    const float* __restrict__ bhh, float* __restrict__ outp)
{
    extern __shared__ __align__(16) char smp[];
    const uint32_t sb = smem_u32(smp);
    const uint32_t WB = sb;
    const uint32_t AB = sb + WB_SZ;
    const int tid = threadIdx.x, lane = tid & 31, wid = tid >> 5;
    const int wm = wid >> 1, wn = wid & 1;
    const int b0 = blockIdx.x * 64, j0 = blockIdx.y * 64;

    // resident Whh: 192 rows x 512 halves
    for (int q = tid; q < 12288; q += 256) {
        const int r = q >> 6, u = q & 63;
        const int g = r >> 6, jj = r & 63;
        uint4 v = *(const uint4*)(g_Whh16 + (size_t)((g << 9) + j0 + jj) * Hdim + u * 8);
        STS16(WB + r * WLD + u * 16, v);
    }
    __syncthreads();

    const uint32_t a_lrow = (wm * 16 + (lane & 15)) * LD64 + (lane >> 4) * 16;
    const uint32_t b_lrowW = ((lane >> 4) * 8 + (lane & 7)) * WLD + ((lane >> 3) & 1) * 16;

    // fixed per-thread output coordinates
    const int jjb = j0 + wn * 32 + (lane & 3) * 2;     // + nf*8
    const int bbA = b0 + wm * 16 + (lane >> 2);        // half 0
    const int bbB = bbA + 8;                           // half 1

    // bhh preloaded once (constant across steps)
    float2 bhh_r[3][4];
    #pragma unroll
    for (int g = 0; g < 3; g++)
        #pragma unroll
        for (int nf = 0; nf < 4; nf++)
            bhh_r[g][nf] = *(const float2*)(bhh + g * Hdim + jjb + nf * 8);

    // h state carried in registers (h0 = 0)
    float hold[2][4][2];
    #pragma unroll
    for (int h = 0; h < 2; h++)
        #pragma unroll
        for (int nf = 0; nf < 4; nf++) { hold[h][nf][0] = 0.0f; hold[h][nf][1] = 0.0f; }

    for (int s = 0; s < Sdim; s++) {
        const int par = s & 1;
        const __half* __restrict__ h16 = g_h16[par];

        float acc[3][4][4];
        #pragma unroll
        for (int g = 0; g < 3; g++)
            #pragma unroll
            for (int b = 0; b < 4; b++)
                #pragma unroll
                for (int d = 0; d < 4; d++) acc[g][b][d] = 0.0f;

        gru_ldA(AB, tid, b0, 0, h16); CP_COMMIT();
        gru_ldA(AB + GAST, tid, b0, 1, h16); CP_COMMIT();

        // prefetch epilogue operands (independent of h) — hidden behind MMA
        const float gate0 = g_G[s * Bdim + bbA];
        const float gate1 = g_G[s * Bdim + bbB];
        __half2 xgp[2][3][4];
        #pragma unroll
        for (int h = 0; h < 2; h++) {
            const __half* xrow = g_xg16 + ((size_t)s * Bdim + (h ? bbB : bbA)) * H3;
            #pragma unroll
            for (int g = 0; g < 3; g++)
                #pragma unroll
                for (int nf = 0; nf < 4; nf++)
                    xgp[h][g][nf] = *(const __half2*)(xrow + g * Hdim + jjb + nf * 8);
        }

        for (int c = 0; c < 8; c++) {
            CP_WAIT1();
            __syncthreads();
            if (c + 2 < 8) gru_ldA(AB + ((c + 2) % 3) * GAST, tid, b0, c + 2, h16);
            CP_COMMIT();
            const uint32_t cur = AB + (c % 3) * GAST;
            const uint32_t koff = c * 128;
            #pragma unroll
            for (int kk = 0; kk < 4; kk++) {
                uint32_t a0, a1, a2, a3;
                LDSM4(a0, a1, a2, a3, cur + a_lrow + kk * 32);
                #pragma unroll
                for (int g = 0; g < 3; g++) {
                    #pragma unroll
                    for (int nfp = 0; nfp < 2; nfp++) {
                        uint32_t b0r, b1r, b2r, b3r;
                        LDSM4(b0r, b1r, b2r, b3r,
                              WB + (g * 64 + wn * 32 + nfp * 16) * WLD + koff + kk * 32 + b_lrowW);
                        mma16816(acc[g][nfp*2],   a0, a1, a2, a3, b0r, b1r);
                        mma16816(acc[g][nfp*2+1], a0, a1, a2, a3, b2r, b3r);
                    }
                }
            }
        }

        // epilogue: all operands in registers
        const int last = (s == Sdim - 1);
        __half* __restrict__ h16N = g_h16[par ^ 1];

        #pragma unroll
        for (int half = 0; half < 2; half++) {
            const int bb = half ? bbB : bbA;
            const float gate = half ? gate1 : gate0;
            #pragma unroll
            for (int nf = 0; nf < 4; nf++) {
                float hn2[2];
                #pragma unroll
                for (int cc = 0; cc < 2; cc++) {
                    const int ai = half * 2 + cc;
                    const float hr = acc[0][nf][ai] + (cc ? bhh_r[0][nf].y : bhh_r[0][nf].x);
                    const float hz = acc[1][nf][ai] + (cc ? bhh_r[1][nf].y : bhh_r[1][nf].x);
                    const float hnv = acc[2][nf][ai] + (cc ? bhh_r[2][nf].y : bhh_r[2][nf].x);
                    const float xr = cc ? __high2float(xgp[half][0][nf]) : __low2float(xgp[half][0][nf]);
                    const float xz = cc ? __high2float(xgp[half][1][nf]) : __low2float(xgp[half][1][nf]);
                    const float xn = cc ? __high2float(xgp[half][2][nf]) : __low2float(xgp[half][2][nf]);
                    const float r = sigmoidf_(xr + hr);
                    const float z = sigmoidf_(xz + hz);
                    const float n = tanhf(xn + r * hnv);
                    const float ho = hold[half][nf][cc];
                    const float hnew = gate * ((1.0f - z) * n + z * ho) + (1.0f - gate) * ho;
                    hold[half][nf][cc] = hnew;
                    hn2[cc] = hnew;
                }
                if (last) {
                    *(float2*)(outp + (size_t)bb * Hdim + jjb + nf * 8) = make_float2(hn2[0], hn2[1]);
                } else {
                    *(__half2*)(h16N + (size_t)bb * Hdim + jjb + nf * 8) = __floats2half2_rn(hn2[0], hn2[1]);
                }
            }
        }

        if (!last) {
            __syncthreads();
            if (tid == 0) {
                __threadfence();
                const unsigned target = (unsigned)(s + 1);
                unsigned arr = atomicAdd(&g_bar_count, 1u);
                if (arr == 127u) {
                    g_bar_count = 0u;
                    __threadfence();
                    atomicExch(&g_bar_gen, target);
                } else {
                    unsigned v;
                    do {
                        asm volatile("ld.acquire.gpu.u32 %0, [%1];" : "=r"(v) : "l"(&g_bar_gen));
                    } while (v < target);
                }
            }
            __syncthreads();
        }
    }
}

// ---------------------------------------------------------------------------
extern "C" void kernel_launch(void* const* d_in, const int* in_sizes, int n_in,
                              void* d_out, int out_size)
{
    const float* C    = (const float*)d_in[0];
    const float* Q    = (const float*)d_in[1];
    const float* PM   = (const float*)d_in[2];
    const float* fc1w = (const float*)d_in[3];
    const float* fc1b = (const float*)d_in[4];
    const float* fc2w = (const float*)d_in[5];
    const float* fc2b = (const float*)d_in[6];
    const float* Wih  = (const float*)d_in[7];
    const float* Whh  = (const float*)d_in[8];
    const float* bih  = (const float*)d_in[9];
    const float* bhh  = (const float*)d_in[10];
    float* out = (float*)d_out;

    static int configured = 0;
    if (!configured) {
        cudaFuncSetAttribute(G_mma,    cudaFuncAttributeMaxDynamicSharedMemorySize, 2 * GST);
        cudaFuncSetAttribute(xg_mma,   cudaFuncAttributeMaxDynamicSharedMemorySize, 4 * XST);
        cudaFuncSetAttribute(gru_pers, cudaFuncAttributeMaxDynamicSharedMemorySize, GRU_SMEM);
        configured = 1;
    }

    zero_init_kernel<<<(Bdim*Hdim + 255)/256, 256>>>();
    cvt_C16_kernel<<<32768, 256>>>(C);
    cvt_W16_kernel<<<1792, 256>>>(Wih, Whh, fc1w);
    G_mma<<<Mrows/128, 256, 2 * GST>>>(C, Q, PM, fc1b, fc2w, fc2b);
    xg_mma<<<dim3(Mrows/128, H3/256), 512, 4 * XST>>>(bih);
    gru_pers<<<dim3(Bdim/64, Hdim/64), 256, GRU_SMEM>>>(bhh, out);
}

// round 9
// speedup vs baseline: 6.1836x; 1.1046x over previous
#include <cuda_runtime.h>
#include <cuda_fp16.h>
#include <math.h>
#include <stdint.h>

#define Hdim 512
#define SHdim 120
#define Bdim 1024
#define Sdim 64
#define H3 1536
#define H4 2048
#define Mrows (Bdim*Sdim)
#define LD 80          // 32-half (64B) rows + 16B pad
#define LD64 144       // 64-half (128B) rows + 16B pad
#define WLD 1040       // resident Whh rows: 512 halves (1024B) + 16B pad

// ----------------------------- device scratch ------------------------------
__device__ float g_G[Sdim*Bdim];
__device__ __half g_xg16[(size_t)Sdim*Bdim*H3];      // xg in fp16
__device__ __half g_h16[2][Bdim*Hdim];               // fp16 MMA operand image
__device__ __half g_C16[(size_t)Mrows*Hdim];         // C fp16
__device__ __half g_Wih16[H3*Hdim];
__device__ __half g_Whh16[H3*Hdim];
__device__ __half g_fc1w16[128*H4];
__device__ unsigned g_grp_cnt[16*32];                // per-b-tile barrier (128B stride)
__device__ unsigned g_grp_gen[16*32];

__device__ __forceinline__ float sigmoidf_(float x){ return 1.0f/(1.0f+expf(-x)); }

// ----------------------------- asm helpers ---------------------------------
__device__ __forceinline__ uint32_t smem_u32(const void* p){
    uint32_t a;
    asm("{ .reg .u64 t; cvta.to.shared.u64 t, %1; cvt.u32.u64 %0, t; }" : "=r"(a) : "l"(p));
    return a;
}
__device__ __forceinline__ void mma16816(float* c, uint32_t a0, uint32_t a1,
                                         uint32_t a2, uint32_t a3,
                                         uint32_t b0, uint32_t b1){
    asm volatile(
        "mma.sync.aligned.m16n8k16.row.col.f32.f16.f16.f32 "
        "{%0,%1,%2,%3},{%4,%5,%6,%7},{%8,%9},{%0,%1,%2,%3};"
        : "+f"(c[0]), "+f"(c[1]), "+f"(c[2]), "+f"(c[3])
        : "r"(a0), "r"(a1), "r"(a2), "r"(a3), "r"(b0), "r"(b1));
}
#define LDSM4(r0,r1,r2,r3, addr) \
    asm volatile("ldmatrix.sync.aligned.m8n8.x4.shared.b16 {%0,%1,%2,%3}, [%4];" \
        : "=r"(r0), "=r"(r1), "=r"(r2), "=r"(r3) : "r"(addr))
#define STS16(dst, v) asm volatile("st.shared.v4.b32 [%0],{%1,%2,%3,%4};" \
        :: "r"(dst), "r"((v).x), "r"((v).y), "r"((v).z), "r"((v).w))
#define CP16(dst, src) asm volatile("cp.async.cg.shared.global [%0], [%1], 16;" \
        :: "r"(dst), "l"(src))
#define CP_COMMIT() asm volatile("cp.async.commit_group;" ::: "memory")
#define CP_WAIT0()  asm volatile("cp.async.wait_group 0;" ::: "memory")
#define CP_WAIT1()  asm volatile("cp.async.wait_group 1;" ::: "memory")
#define CP_WAIT2()  asm volatile("cp.async.wait_group 2;" ::: "memory")

// ----------------------------- init / convert ------------------------------
__global__ void zero_init_kernel(){
    int i = blockIdx.x * blockDim.x + threadIdx.x;
    if (i < Bdim * Hdim) g_h16[0][i] = __float2half_rn(0.0f);
    if (i < 16*32) { g_grp_cnt[i] = 0u; g_grp_gen[i] = 0u; }
}
__device__ __forceinline__ uint2 cvt4h(float4 v){
    __half2 h0(__float2half_rn(v.x), __float2half_rn(v.y));
    __half2 h1(__float2half_rn(v.z), __float2half_rn(v.w));
    uint2 o; o.x = *(uint32_t*)&h0; o.y = *(uint32_t*)&h1; return o;
}
__global__ void cvt_C16_kernel(const float* __restrict__ src){
    size_t i = (size_t)blockIdx.x * blockDim.x + threadIdx.x;   // 8388608 float4
    ((uint2*)g_C16)[i] = cvt4h(((const float4*)src)[i]);
}
__global__ void cvt_W16_kernel(const float* __restrict__ wih,
                               const float* __restrict__ whh,
                               const float* __restrict__ fc1w){
    int i = blockIdx.x * blockDim.x + threadIdx.x;
    const int nW = H3 * Hdim / 4;                    // 196608
    const int nF = SHdim * H4 / 4;                   // 61440
    if (i < nW) {
        ((uint2*)g_Wih16)[i] = cvt4h(((const float4*)wih)[i]);
    } else if (i < 2*nW) {
        int j = i - nW;
        ((uint2*)g_Whh16)[j] = cvt4h(((const float4*)whh)[j]);
    } else if (i < 2*nW + nF) {
        int j = i - 2*nW;
        ((uint2*)g_fc1w16)[j] = cvt4h(((const float4*)fc1w)[j]);
    } else {
        int j = i - 2*nW - nF;                       // 4096 pad uint2
        ((uint2*)g_fc1w16)[nF + j] = make_uint2(0u, 0u);
    }
}

// ---------------------------------------------------------------------------
// Gate network: one C16 read per chunk feeds all 4 feat parts.
// CTA m-tile 128, n 128 (120 real), 256 threads; 16 chunks of k32, 4 parts each.
// ---------------------------------------------------------------------------
#define GAp (128*LD)               // 10240 per part image
#define GA4 (4*GAp)                // 40960 A block (4 parts)
#define GST3 (GA4 + 4*GAp)         // stage = A(4) + B(4) = 81920

__global__ __launch_bounds__(256, 1) void G_mma(
    const float* __restrict__ Q, const float* __restrict__ PM,
    const float* __restrict__ fc1b, const float* __restrict__ fc2w,
    const float* __restrict__ fc2b)
{
    extern __shared__ __align__(16) char smg2[];
    __shared__ __align__(16) float sQP[2][2][Hdim];   // [q/pm][b_local][k]
    const uint32_t sb = smem_u32(smg2);
    const int tid = threadIdx.x, lane = tid & 31, wm = tid >> 5;
    const int m0 = blockIdx.x * 128;

    {
        const int b_base = m0 >> 6;
        for (int q = tid; q < 2 * Hdim / 4; q += 256) {
            const int bl = q / (Hdim/4), u = q % (Hdim/4);
            *(float4*)&sQP[0][bl][u*4] = *(const float4*)(Q  + (size_t)(b_base+bl)*Hdim + u*4);
            *(float4*)&sQP[1][bl][u*4] = *(const float4*)(PM + (size_t)(b_base+bl)*Hdim + u*4);
        }
    }
    __syncthreads();

    float acc[16][4];
    #pragma unroll
    for (int a = 0; a < 16; a++)
        #pragma unroll
        for (int d = 0; d < 4; d++) acc[a][d] = 0.0f;

    auto G_fetchC = [&](int c, uint4* rr) {
        const int base0 = c * 32;
        #pragma unroll
        for (int i = 0; i < 2; i++) {
            const int idx = tid + i * 256;          // 512 u4 = 128 rows x 4
            const int r = idx >> 2, u = idx & 3;
            rr[i] = *(const uint4*)(g_C16 + (size_t)(m0 + r) * Hdim + base0 + u * 8);
        }
    };
    auto G_storeA = [&](int c, uint32_t buf, const uint4* rr) {
        const int base0 = c * 32;
        #pragma unroll
        for (int i = 0; i < 2; i++) {
            const int idx = tid + i * 256;
            const int r = idx >> 2, u = idx & 3;
            const __half* ch = (const __half*)&rr[i];
            float cf[8];
            #pragma unroll
            for (int j = 0; j < 8; j++) cf[j] = __half2float(ch[j]);
            const float* qv = &sQP[0][r >> 6][base0 + u * 8];
            const float* pv = &sQP[1][r >> 6][base0 + u * 8];
            #pragma unroll
            for (int part = 0; part < 4; part++) {
                const float* vv = (part & 1) ? pv : qv;
                uint32_t o[4];
                #pragma unroll
                for (int j = 0; j < 4; j++) {
                    const float x0 = (part < 2) ? cf[2*j]   * vv[2*j]
                                                : fabsf(cf[2*j]   - vv[2*j]);
                    const float x1 = (part < 2) ? cf[2*j+1] * vv[2*j+1]
                                                : fabsf(cf[2*j+1] - vv[2*j+1]);
                    const __half2 hh = __floats2half2_rn(x0, x1);
                    o[j] = *(const uint32_t*)&hh;
                }
                const uint4 v4 = make_uint4(o[0], o[1], o[2], o[3]);
                STS16(buf + part * GAp + r * LD + u * 16, v4);
            }
        }
    };
    auto G_cpB = [&](int c, uint32_t buf) {
        const int base0 = c * 32;
        #pragma unroll
        for (int i = 0; i < 8; i++) {               // 2048 u4 (4 parts x 512)
            const int q = tid + i * 256;
            const int part = q >> 9, rem = q & 511;
            const int r = rem >> 2, u = rem & 3;
            CP16(buf + GA4 + part * GAp + r * LD + u * 16,
                 g_fc1w16 + (size_t)r * H4 + part * 512 + base0 + u * 8);
        }
    };

    uint4 rr[2];
    G_fetchC(0, rr);
    G_cpB(0, sb);
    CP_COMMIT();
    G_storeA(0, sb, rr);
    CP_WAIT0();
    __syncthreads();

    const uint32_t a_lrow = (wm * 16 + (lane & 15)) * LD + (lane >> 4) * 16;
    const uint32_t b_lrow = ((lane >> 4) * 8 + (lane & 7)) * LD + ((lane >> 3) & 1) * 16;

    for (int c = 0; c < 16; c++) {
        const uint32_t cur = sb + (c & 1) * GST3;
        const uint32_t nxt = sb + ((c + 1) & 1) * GST3;
        if (c < 15) {
            G_fetchC(c + 1, rr);
            G_cpB(c + 1, nxt);
        }
        CP_COMMIT();
        #pragma unroll
        for (int part = 0; part < 4; part++) {
            #pragma unroll
            for (int kk = 0; kk < 2; kk++) {
                uint32_t b[8][4];
                #pragma unroll
                for (int nb = 0; nb < 8; nb++)
                    LDSM4(b[nb][0], b[nb][1], b[nb][2], b[nb][3],
                          cur + GA4 + part * GAp + (nb * 16) * LD + kk * 32 + b_lrow);
                uint32_t a0, a1, a2, a3;
                LDSM4(a0, a1, a2, a3, cur + part * GAp + a_lrow + kk * 32);
                #pragma unroll
                for (int nb = 0; nb < 8; nb++) {
                    mma16816(acc[nb*2],   a0, a1, a2, a3, b[nb][0], b[nb][1]);
                    mma16816(acc[nb*2+1], a0, a1, a2, a3, b[nb][2], b[nb][3]);
                }
            }
        }
        if (c < 15) G_storeA(c + 1, nxt, rr);
        CP_WAIT0();
        __syncthreads();
    }

    const float fc2b0 = fc2b[0];
    #pragma unroll
    for (int half = 0; half < 2; half++) {
        float partial = 0.0f;
        #pragma unroll
        for (int nb = 0; nb < 16; nb++) {
            #pragma unroll
            for (int cc = 0; cc < 2; cc++) {
                const int n = nb * 8 + (lane & 3) * 2 + cc;
                if (n < SHdim)
                    partial += fc2w[n] * tanhf(acc[nb][half*2+cc] + fc1b[n]);
            }
        }
        partial += __shfl_xor_sync(0xffffffffu, partial, 1);
        partial += __shfl_xor_sync(0xffffffffu, partial, 2);
        if ((lane & 3) == 0) {
            const int m = m0 + wm * 16 + (lane >> 2) + half * 8;
            g_G[(m & 63) * Bdim + (m >> 6)] = sigmoidf_(partial + fc2b0);
        }
    }
}

// ---------------------------------------------------------------------------
// xg = C @ Wih^T + b (fp16, single term). CTA 128m x 256n, 512 threads,
// cp.async 4-stage, 8 chunks of k64. Output fp16.
// ---------------------------------------------------------------------------
#define XA2 (128*LD64)             // 18432
#define XST (XA2 + 256*LD64)       // 55296

__device__ __forceinline__ void xg_ld(uint32_t buf, int tid, int m0, int n0, int c){
    const int k0 = c * 64;
    #pragma unroll
    for (int i = 0; i < 2; i++) {            // A: 1024 u4
        const int q = tid + i * 512;
        const int r = q >> 3, u = q & 7;
        CP16(buf + r * LD64 + u * 16, g_C16 + (size_t)(m0 + r) * Hdim + k0 + u * 8);
    }
    #pragma unroll
    for (int i = 0; i < 4; i++) {            // B: 2048 u4
        const int q = tid + i * 512;
        const int r = q >> 3, u = q & 7;
        CP16(buf + XA2 + r * LD64 + u * 16, g_Wih16 + (size_t)(n0 + r) * Hdim + k0 + u * 8);
    }
}

__global__ __launch_bounds__(512, 1) void xg_mma(const float* __restrict__ bih)
{
    extern __shared__ __align__(16) char smx[];
    const uint32_t sb = smem_u32(smx);
    const int tid = threadIdx.x, lane = tid & 31, wid = tid >> 5;
    const int wm = wid >> 3, wn = wid & 7;
    const int m0 = blockIdx.x * 128, n0 = blockIdx.y * 256;

    float acc[4][4][4];
    #pragma unroll
    for (int a = 0; a < 4; a++)
        #pragma unroll
        for (int b = 0; b < 4; b++)
            #pragma unroll
            for (int d = 0; d < 4; d++) acc[a][b][d] = 0.0f;

    xg_ld(sb, tid, m0, n0, 0); CP_COMMIT();
    xg_ld(sb + XST, tid, m0, n0, 1); CP_COMMIT();
    xg_ld(sb + 2*XST, tid, m0, n0, 2); CP_COMMIT();

    const uint32_t a_lrow = (lane & 15) * LD64 + (lane >> 4) * 16;
    const uint32_t b_lrow = ((lane >> 4) * 8 + (lane & 7)) * LD64 + ((lane >> 3) & 1) * 16;

    for (int c = 0; c < 8; c++) {
        CP_WAIT2();
        __syncthreads();
        if (c + 3 < 8) xg_ld(sb + ((c + 3) & 3) * XST, tid, m0, n0, c + 3);
        CP_COMMIT();
        const uint32_t cur = sb + (c & 3) * XST;
        #pragma unroll
        for (int kk = 0; kk < 4; kk++) {
            uint32_t a[4][4];
            #pragma unroll
            for (int mf = 0; mf < 4; mf++)
                LDSM4(a[mf][0], a[mf][1], a[mf][2], a[mf][3],
                      cur + (wm * 64 + mf * 16) * LD64 + kk * 32 + a_lrow);
            #pragma unroll
            for (int nfp = 0; nfp < 2; nfp++) {
                uint32_t b0, b1, b2, b3;
                LDSM4(b0, b1, b2, b3,
                      cur + XA2 + (wn * 32 + nfp * 16) * LD64 + kk * 32 + b_lrow);
                #pragma unroll
                for (int mf = 0; mf < 4; mf++) {
                    mma16816(acc[mf][nfp*2],   a[mf][0], a[mf][1], a[mf][2], a[mf][3], b0, b1);
                    mma16816(acc[mf][nfp*2+1], a[mf][0], a[mf][1], a[mf][2], a[mf][3], b2, b3);
                }
            }
        }
    }

    #pragma unroll
    for (int mf = 0; mf < 4; mf++) {
        #pragma unroll
        for (int half = 0; half < 2; half++) {
            const int m = m0 + wm * 64 + mf * 16 + (lane >> 2) + half * 8;
            const size_t ob = ((size_t)(m & 63) * Bdim + (m >> 6)) * H3;
            #pragma unroll
            for (int nf = 0; nf < 4; nf++) {
                const int jj = n0 + wn * 32 + nf * 8 + (lane & 3) * 2;
                const float ox = acc[mf][nf][half*2+0] + bih[jj];
                const float oy = acc[mf][nf][half*2+1] + bih[jj+1];
                *(__half2*)(g_xg16 + ob + jj) = __floats2half2_rn(ox, oy);
            }
        }
    }
}

// ---------------------------------------------------------------------------
// Persistent GRU: Whh resident; register-carried h; per-b-tile 8-CTA barriers.
// ---------------------------------------------------------------------------
#define WB_SZ (192*WLD)            // 199680
#define GAST (64*LD64)             // 9216/stage, 3 stages
#define GRU_SMEM (WB_SZ + 3*GAST)  // 227328

__device__ __forceinline__ void gru_ldA(uint32_t dst, int tid, int b0, int c,
                                        const __half* __restrict__ h16){
    const int k0 = c * 64;
    #pragma unroll
    for (int i = 0; i < 2; i++) {            // 512 u4
        const int q = tid + i * 256;
        const int r = q >> 3, u = q & 7;
        CP16(dst + r * LD64 + u * 16, h16 + (size_t)(b0 + r) * Hdim + k0 + u * 8);
    }
}

__global__ __launch_bounds__(256, 1) void gru_pers(
    const float* __restrict__ bhh, float* __restrict__ outp)
{
    extern __shared__ __align__(16) char smp[];
    const uint32_t sb = smem_u32(smp);
    const uint32_t WB = sb;
    const uint32_t AB = sb + WB_SZ;
    const int tid = threadIdx.x, lane = tid & 31, wid = tid >> 5;
    const int wm = wid >> 1, wn = wid & 1;
    const int bt = blockIdx.x;                       // b-tile index (group id)
    const int b0 = bt * 64, j0 = blockIdx.y * 64;
    unsigned* const cnt = &g_grp_cnt[bt * 32];
    unsigned* const gen = &g_grp_gen[bt * 32];

    // resident Whh: 192 rows x 512 halves
    for (int q = tid; q < 12288; q += 256) {
        const int r = q >> 6, u = q & 63;
        const int g = r >> 6, jj = r & 63;
        uint4 v = *(const uint4*)(g_Whh16 + (size_t)((g << 9) + j0 + jj) * Hdim + u * 8);
        STS16(WB + r * WLD + u * 16, v);
    }
    __syncthreads();

    const uint32_t a_lrow = (wm * 16 + (lane & 15)) * LD64 + (lane >> 4) * 16;
    const uint32_t b_lrowW = ((lane >> 4) * 8 + (lane & 7)) * WLD + ((lane >> 3) & 1) * 16;

    const int jjb = j0 + wn * 32 + (lane & 3) * 2;
    const int bbA = b0 + wm * 16 + (lane >> 2);
    const int bbB = bbA + 8;

    float2 bhh_r[3][4];
    #pragma unroll
    for (int g = 0; g < 3; g++)
        #pragma unroll
        for (int nf = 0; nf < 4; nf++)
            bhh_r[g][nf] = *(const float2*)(bhh + g * Hdim + jjb + nf * 8);

    float hold[2][4][2];
    #pragma unroll
    for (int h = 0; h < 2; h++)
        #pragma unroll
        for (int nf = 0; nf < 4; nf++) { hold[h][nf][0] = 0.0f; hold[h][nf][1] = 0.0f; }

    for (int s = 0; s < Sdim; s++) {
        const int par = s & 1;
        const __half* __restrict__ h16 = g_h16[par];

        float acc[3][4][4];
        #pragma unroll
        for (int g = 0; g < 3; g++)
            #pragma unroll
            for (int b = 0; b < 4; b++)
                #pragma unroll
                for (int d = 0; d < 4; d++) acc[g][b][d] = 0.0f;

        gru_ldA(AB, tid, b0, 0, h16); CP_COMMIT();
        gru_ldA(AB + GAST, tid, b0, 1, h16); CP_COMMIT();

        const float gate0 = g_G[s * Bdim + bbA];
        const float gate1 = g_G[s * Bdim + bbB];
        __half2 xgp[2][3][4];
        #pragma unroll
        for (int h = 0; h < 2; h++) {
            const __half* xrow = g_xg16 + ((size_t)s * Bdim + (h ? bbB : bbA)) * H3;
            #pragma unroll
            for (int g = 0; g < 3; g++)
                #pragma unroll
                for (int nf = 0; nf < 4; nf++)
                    xgp[h][g][nf] = *(const __half2*)(xrow + g * Hdim + jjb + nf * 8);
        }

        for (int c = 0; c < 8; c++) {
            CP_WAIT1();
            __syncthreads();
            if (c + 2 < 8) gru_ldA(AB + ((c + 2) % 3) * GAST, tid, b0, c + 2, h16);
            CP_COMMIT();
            const uint32_t cur = AB + (c % 3) * GAST;
            const uint32_t koff = c * 128;
            #pragma unroll
            for (int kk = 0; kk < 4; kk++) {
                uint32_t a0, a1, a2, a3;
                LDSM4(a0, a1, a2, a3, cur + a_lrow + kk * 32);
                #pragma unroll
                for (int g = 0; g < 3; g++) {
                    #pragma unroll
                    for (int nfp = 0; nfp < 2; nfp++) {
                        uint32_t b0r, b1r, b2r, b3r;
                        LDSM4(b0r, b1r, b2r, b3r,
                              WB + (g * 64 + wn * 32 + nfp * 16) * WLD + koff + kk * 32 + b_lrowW);
                        mma16816(acc[g][nfp*2],   a0, a1, a2, a3, b0r, b1r);
                        mma16816(acc[g][nfp*2+1], a0, a1, a2, a3, b2r, b3r);
                    }
                }
            }
        }

        const int last = (s == Sdim - 1);
        __half* __restrict__ h16N = g_h16[par ^ 1];

        #pragma unroll
        for (int half = 0; half < 2; half++) {
            const int bb = half ? bbB : bbA;
            const float gate = half ? gate1 : gate0;
            #pragma unroll
            for (int nf = 0; nf < 4; nf++) {
                float hn2[2];
                #pragma unroll
                for (int cc = 0; cc < 2; cc++) {
                    const int ai = half * 2 + cc;
                    const float hr = acc[0][nf][ai] + (cc ? bhh_r[0][nf].y : bhh_r[0][nf].x);
                    const float hz = acc[1][nf][ai] + (cc ? bhh_r[1][nf].y : bhh_r[1][nf].x);
                    const float hnv = acc[2][nf][ai] + (cc ? bhh_r[2][nf].y : bhh_r[2][nf].x);
                    const float xr = cc ? __high2float(xgp[half][0][nf]) : __low2float(xgp[half][0][nf]);
                    const float xz = cc ? __high2float(xgp[half][1][nf]) : __low2float(xgp[half][1][nf]);
                    const float xn = cc ? __high2float(xgp[half][2][nf]) : __low2float(xgp[half][2][nf]);
                    const float r = sigmoidf_(xr + hr);
                    const float z = sigmoidf_(xz + hz);
                    const float n = tanhf(xn + r * hnv);
                    const float ho = hold[half][nf][cc];
                    const float hnew = gate * ((1.0f - z) * n + z * ho) + (1.0f - gate) * ho;
                    hold[half][nf][cc] = hnew;
                    hn2[cc] = hnew;
                }
                if (last) {
                    *(float2*)(outp + (size_t)bb * Hdim + jjb + nf * 8) = make_float2(hn2[0], hn2[1]);
                } else {
                    *(__half2*)(h16N + (size_t)bb * Hdim + jjb + nf * 8) = __floats2half2_rn(hn2[0], hn2[1]);
                }
            }
        }

        if (!last) {
            __syncthreads();
            if (tid == 0) {
                __threadfence();
                const unsigned target = (unsigned)(s + 1);
                unsigned arr = atomicAdd(cnt, 1u);
                if (arr == 7u) {
                    *cnt = 0u;
                    __threadfence();
                    atomicExch(gen, target);
                } else {
                    unsigned v;
                    do {
                        asm volatile("ld.acquire.gpu.u32 %0, [%1];" : "=r"(v) : "l"(gen));
                    } while (v < target);
                }
            }
            __syncthreads();
        }
    }
}

// ---------------------------------------------------------------------------
extern "C" void kernel_launch(void* const* d_in, const int* in_sizes, int n_in,
                              void* d_out, int out_size)
{
    const float* C    = (const float*)d_in[0];
    const float* Q    = (const float*)d_in[1];
    const float* PM   = (const float*)d_in[2];
    const float* fc1w = (const float*)d_in[3];
    const float* fc1b = (const float*)d_in[4];
    const float* fc2w = (const float*)d_in[5];
    const float* fc2b = (const float*)d_in[6];
    const float* Wih  = (const float*)d_in[7];
    const float* Whh  = (const float*)d_in[8];
    const float* bih  = (const float*)d_in[9];
    const float* bhh  = (const float*)d_in[10];
    float* out = (float*)d_out;

    static int configured = 0;
    if (!configured) {
        cudaFuncSetAttribute(G_mma,    cudaFuncAttributeMaxDynamicSharedMemorySize, 2 * GST3);
        cudaFuncSetAttribute(xg_mma,   cudaFuncAttributeMaxDynamicSharedMemorySize, 4 * XST);
        cudaFuncSetAttribute(gru_pers, cudaFuncAttributeMaxDynamicSharedMemorySize, GRU_SMEM);
        configured = 1;
    }

    zero_init_kernel<<<(Bdim*Hdim + 255)/256, 256>>>();
    cvt_C16_kernel<<<32768, 256>>>(C);
    cvt_W16_kernel<<<1792, 256>>>(Wih, Whh, fc1w);
    G_mma<<<Mrows/128, 256, 2 * GST3>>>(Q, PM, fc1b, fc2w, fc2b);
    xg_mma<<<dim3(Mrows/128, H3/256), 512, 4 * XST>>>(bih);
    gru_pers<<<dim3(Bdim/64, Hdim/64), 256, GRU_SMEM>>>(bhh, out);
}

// round 10
// speedup vs baseline: 7.1451x; 1.1555x over previous
#include <cuda_runtime.h>
#include <cuda_fp16.h>
#include <math.h>
#include <stdint.h>

#define Hdim 512
#define SHdim 120
#define Bdim 1024
#define Sdim 64
#define H3 1536
#define H4 2048
#define Mrows (Bdim*Sdim)
#define LD 80          // 32-half (64B) rows + 16B pad
#define LD64 144       // 64-half (128B) rows + 16B pad
#define WLD 1040       // resident Whh rows: 512 halves (1024B) + 16B pad

// ----------------------------- device scratch ------------------------------
__device__ float g_G[Sdim*Bdim];
__device__ __half g_xg16[(size_t)Sdim*Bdim*H3];      // xg in fp16
__device__ __half g_h16[2][Bdim*Hdim];               // fp16 MMA operand image
__device__ __half g_C16[(size_t)Mrows*Hdim];         // C fp16
__device__ __half g_Wih16[H3*Hdim];
__device__ __half g_Whh16[H3*Hdim];
__device__ __half g_fc1w16[128*H4];
__device__ unsigned g_grp_cnt[16*32];                // per-b-tile barrier (128B stride)
__device__ unsigned g_grp_gen[16*32];

// fast transcendentals: rel err ~1e-6 (EX2/RCP MUFU) — far below fp16 noise
__device__ __forceinline__ float sigmoidf_(float x){
    return __fdividef(1.0f, 1.0f + __expf(-x));
}
__device__ __forceinline__ float tanhf_(float x){
    return __fdividef(2.0f, 1.0f + __expf(-2.0f * x)) - 1.0f;
}

// ----------------------------- asm helpers ---------------------------------
__device__ __forceinline__ uint32_t smem_u32(const void* p){
    uint32_t a;
    asm("{ .reg .u64 t; cvta.to.shared.u64 t, %1; cvt.u32.u64 %0, t; }" : "=r"(a) : "l"(p));
    return a;
}
__device__ __forceinline__ void mma16816(float* c, uint32_t a0, uint32_t a1,
                                         uint32_t a2, uint32_t a3,
                                         uint32_t b0, uint32_t b1){
    asm volatile(
        "mma.sync.aligned.m16n8k16.row.col.f32.f16.f16.f32 "
        "{%0,%1,%2,%3},{%4,%5,%6,%7},{%8,%9},{%0,%1,%2,%3};"
        : "+f"(c[0]), "+f"(c[1]), "+f"(c[2]), "+f"(c[3])
        : "r"(a0), "r"(a1), "r"(a2), "r"(a3), "r"(b0), "r"(b1));
}
#define LDSM4(r0,r1,r2,r3, addr) \
    asm volatile("ldmatrix.sync.aligned.m8n8.x4.shared.b16 {%0,%1,%2,%3}, [%4];" \
        : "=r"(r0), "=r"(r1), "=r"(r2), "=r"(r3) : "r"(addr))
#define STS16(dst, v) asm volatile("st.shared.v4.b32 [%0],{%1,%2,%3,%4};" \
        :: "r"(dst), "r"((v).x), "r"((v).y), "r"((v).z), "r"((v).w))
#define CP16(dst, src) asm volatile("cp.async.cg.shared.global [%0], [%1], 16;" \
        :: "r"(dst), "l"(src))
#define CP_COMMIT() asm volatile("cp.async.commit_group;" ::: "memory")
#define CP_WAIT0()  asm volatile("cp.async.wait_group 0;" ::: "memory")
#define CP_WAIT1()  asm volatile("cp.async.wait_group 1;" ::: "memory")
#define CP_WAIT2()  asm volatile("cp.async.wait_group 2;" ::: "memory")

// ----------------------------- init / convert ------------------------------
__global__ void zero_init_kernel(){
    int i = blockIdx.x * blockDim.x + threadIdx.x;
    if (i < Bdim * Hdim) g_h16[0][i] = __float2half_rn(0.0f);
    if (i < 16*32) { g_grp_cnt[i] = 0u; g_grp_gen[i] = 0u; }
}
__device__ __forceinline__ uint2 cvt4h(float4 v){
    __half2 h0(__float2half_rn(v.x), __float2half_rn(v.y));
    __half2 h1(__float2half_rn(v.z), __float2half_rn(v.w));
    uint2 o; o.x = *(uint32_t*)&h0; o.y = *(uint32_t*)&h1; return o;
}
__global__ void cvt_C16_kernel(const float* __restrict__ src){
    size_t i = (size_t)blockIdx.x * blockDim.x + threadIdx.x;   // 8388608 float4
    ((uint2*)g_C16)[i] = cvt4h(((const float4*)src)[i]);
}
__global__ void cvt_W16_kernel(const float* __restrict__ wih,
                               const float* __restrict__ whh,
                               const float* __restrict__ fc1w){
    int i = blockIdx.x * blockDim.x + threadIdx.x;
    const int nW = H3 * Hdim / 4;                    // 196608
    const int nF = SHdim * H4 / 4;                   // 61440
    if (i < nW) {
        ((uint2*)g_Wih16)[i] = cvt4h(((const float4*)wih)[i]);
    } else if (i < 2*nW) {
        int j = i - nW;
        ((uint2*)g_Whh16)[j] = cvt4h(((const float4*)whh)[j]);
    } else if (i < 2*nW + nF) {
        int j = i - 2*nW;
        ((uint2*)g_fc1w16)[j] = cvt4h(((const float4*)fc1w)[j]);
    } else {
        int j = i - 2*nW - nF;                       // 4096 pad uint2
        ((uint2*)g_fc1w16)[nF + j] = make_uint2(0u, 0u);
    }
}

// ---------------------------------------------------------------------------
// Gate network: one C16 read per chunk feeds all 4 feat parts.
// CTA m-tile 128, n 128 (120 real), 256 threads; 16 chunks of k32, 4 parts each.
// ---------------------------------------------------------------------------
#define GAp (128*LD)               // 10240 per part image
#define GA4 (4*GAp)                // 40960 A block (4 parts)
#define GST3 (GA4 + 4*GAp)         // stage = A(4) + B(4) = 81920

__global__ __launch_bounds__(256, 1) void G_mma(
    const float* __restrict__ Q, const float* __restrict__ PM,
    const float* __restrict__ fc1b, const float* __restrict__ fc2w,
    const float* __restrict__ fc2b)
{
    extern __shared__ __align__(16) char smg2[];
    __shared__ __align__(16) float sQP[2][2][Hdim];   // [q/pm][b_local][k]
    const uint32_t sb = smem_u32(smg2);
    const int tid = threadIdx.x, lane = tid & 31, wm = tid >> 5;
    const int m0 = blockIdx.x * 128;

    {
        const int b_base = m0 >> 6;
        for (int q = tid; q < 2 * Hdim / 4; q += 256) {
            const int bl = q / (Hdim/4), u = q % (Hdim/4);
            *(float4*)&sQP[0][bl][u*4] = *(const float4*)(Q  + (size_t)(b_base+bl)*Hdim + u*4);
            *(float4*)&sQP[1][bl][u*4] = *(const float4*)(PM + (size_t)(b_base+bl)*Hdim + u*4);
        }
    }
    __syncthreads();

    float acc[16][4];
    #pragma unroll
    for (int a = 0; a < 16; a++)
        #pragma unroll
        for (int d = 0; d < 4; d++) acc[a][d] = 0.0f;

    auto G_fetchC = [&](int c, uint4* rr) {
        const int base0 = c * 32;
        #pragma unroll
        for (int i = 0; i < 2; i++) {
            const int idx = tid + i * 256;          // 512 u4 = 128 rows x 4
            const int r = idx >> 2, u = idx & 3;
            rr[i] = *(const uint4*)(g_C16 + (size_t)(m0 + r) * Hdim + base0 + u * 8);
        }
    };
    auto G_storeA = [&](int c, uint32_t buf, const uint4* rr) {
        const int base0 = c * 32;
        #pragma unroll
        for (int i = 0; i < 2; i++) {
            const int idx = tid + i * 256;
            const int r = idx >> 2, u = idx & 3;
            const __half* ch = (const __half*)&rr[i];
            float cf[8];
            #pragma unroll
            for (int j = 0; j < 8; j++) cf[j] = __half2float(ch[j]);
            const float* qv = &sQP[0][r >> 6][base0 + u * 8];
            const float* pv = &sQP[1][r >> 6][base0 + u * 8];
            #pragma unroll
            for (int part = 0; part < 4; part++) {
                const float* vv = (part & 1) ? pv : qv;
                uint32_t o[4];
                #pragma unroll
                for (int j = 0; j < 4; j++) {
                    const float x0 = (part < 2) ? cf[2*j]   * vv[2*j]
                                                : fabsf(cf[2*j]   - vv[2*j]);
                    const float x1 = (part < 2) ? cf[2*j+1] * vv[2*j+1]
                                                : fabsf(cf[2*j+1] - vv[2*j+1]);
                    const __half2 hh = __floats2half2_rn(x0, x1);
                    o[j] = *(const uint32_t*)&hh;
                }
                const uint4 v4 = make_uint4(o[0], o[1], o[2], o[3]);
                STS16(buf + part * GAp + r * LD + u * 16, v4);
            }
        }
    };
    auto G_cpB = [&](int c, uint32_t buf) {
        const int base0 = c * 32;
        #pragma unroll
        for (int i = 0; i < 8; i++) {               // 2048 u4 (4 parts x 512)
            const int q = tid + i * 256;
            const int part = q >> 9, rem = q & 511;
            const int r = rem >> 2, u = rem & 3;
            CP16(buf + GA4 + part * GAp + r * LD + u * 16,
                 g_fc1w16 + (size_t)r * H4 + part * 512 + base0 + u * 8);
        }
    };

    uint4 rr[2];
    G_fetchC(0, rr);
    G_cpB(0, sb);
    CP_COMMIT();
    G_storeA(0, sb, rr);
    CP_WAIT0();
    __syncthreads();

    const uint32_t a_lrow = (wm * 16 + (lane & 15)) * LD + (lane >> 4) * 16;
    const uint32_t b_lrow = ((lane >> 4) * 8 + (lane & 7)) * LD + ((lane >> 3) & 1) * 16;

    for (int c = 0; c < 16; c++) {
        const uint32_t cur = sb + (c & 1) * GST3;
        const uint32_t nxt = sb + ((c + 1) & 1) * GST3;
        if (c < 15) {
            G_fetchC(c + 1, rr);
            G_cpB(c + 1, nxt);
        }
        CP_COMMIT();
        #pragma unroll
        for (int part = 0; part < 4; part++) {
            #pragma unroll
            for (int kk = 0; kk < 2; kk++) {
                uint32_t b[8][4];
                #pragma unroll
                for (int nb = 0; nb < 8; nb++)
                    LDSM4(b[nb][0], b[nb][1], b[nb][2], b[nb][3],
                          cur + GA4 + part * GAp + (nb * 16) * LD + kk * 32 + b_lrow);
                uint32_t a0, a1, a2, a3;
                LDSM4(a0, a1, a2, a3, cur + part * GAp + a_lrow + kk * 32);
                #pragma unroll
                for (int nb = 0; nb < 8; nb++) {
                    mma16816(acc[nb*2],   a0, a1, a2, a3, b[nb][0], b[nb][1]);
                    mma16816(acc[nb*2+1], a0, a1, a2, a3, b[nb][2], b[nb][3]);
                }
            }
        }
        if (c < 15) G_storeA(c + 1, nxt, rr);
        CP_WAIT0();
        __syncthreads();
    }

    const float fc2b0 = fc2b[0];
    #pragma unroll
    for (int half = 0; half < 2; half++) {
        float partial = 0.0f;
        #pragma unroll
        for (int nb = 0; nb < 16; nb++) {
            #pragma unroll
            for (int cc = 0; cc < 2; cc++) {
                const int n = nb * 8 + (lane & 3) * 2 + cc;
                if (n < SHdim)
                    partial += fc2w[n] * tanhf_(acc[nb][half*2+cc] + fc1b[n]);
            }
        }
        partial += __shfl_xor_sync(0xffffffffu, partial, 1);
        partial += __shfl_xor_sync(0xffffffffu, partial, 2);
        if ((lane & 3) == 0) {
            const int m = m0 + wm * 16 + (lane >> 2) + half * 8;
            g_G[(m & 63) * Bdim + (m >> 6)] = sigmoidf_(partial + fc2b0);
        }
    }
}

// ---------------------------------------------------------------------------
// xg = C @ Wih^T + b (fp16, single term). CTA 128m x 256n, 512 threads,
// cp.async 4-stage, 8 chunks of k64. Output fp16.
// ---------------------------------------------------------------------------
#define XA2 (128*LD64)             // 18432
#define XST (XA2 + 256*LD64)       // 55296

__device__ __forceinline__ void xg_ld(uint32_t buf, int tid, int m0, int n0, int c){
    const int k0 = c * 64;
    #pragma unroll
    for (int i = 0; i < 2; i++) {            // A: 1024 u4
        const int q = tid + i * 512;
        const int r = q >> 3, u = q & 7;
        CP16(buf + r * LD64 + u * 16, g_C16 + (size_t)(m0 + r) * Hdim + k0 + u * 8);
    }
    #pragma unroll
    for (int i = 0; i < 4; i++) {            // B: 2048 u4
        const int q = tid + i * 512;
        const int r = q >> 3, u = q & 7;
        CP16(buf + XA2 + r * LD64 + u * 16, g_Wih16 + (size_t)(n0 + r) * Hdim + k0 + u * 8);
    }
}

__global__ __launch_bounds__(512, 1) void xg_mma(const float* __restrict__ bih)
{
    extern __shared__ __align__(16) char smx[];
    const uint32_t sb = smem_u32(smx);
    const int tid = threadIdx.x, lane = tid & 31, wid = tid >> 5;
    const int wm = wid >> 3, wn = wid & 7;
    const int m0 = blockIdx.x * 128, n0 = blockIdx.y * 256;

    float acc[4][4][4];
    #pragma unroll
    for (int a = 0; a < 4; a++)
        #pragma unroll
        for (int b = 0; b < 4; b++)
            #pragma unroll
            for (int d = 0; d < 4; d++) acc[a][b][d] = 0.0f;

    xg_ld(sb, tid, m0, n0, 0); CP_COMMIT();
    xg_ld(sb + XST, tid, m0, n0, 1); CP_COMMIT();
    xg_ld(sb + 2*XST, tid, m0, n0, 2); CP_COMMIT();

    const uint32_t a_lrow = (lane & 15) * LD64 + (lane >> 4) * 16;
    const uint32_t b_lrow = ((lane >> 4) * 8 + (lane & 7)) * LD64 + ((lane >> 3) & 1) * 16;

    for (int c = 0; c < 8; c++) {
        CP_WAIT2();
        __syncthreads();
        if (c + 3 < 8) xg_ld(sb + ((c + 3) & 3) * XST, tid, m0, n0, c + 3);
        CP_COMMIT();
        const uint32_t cur = sb + (c & 3) * XST;
        #pragma unroll
        for (int kk = 0; kk < 4; kk++) {
            uint32_t a[4][4];
            #pragma unroll
            for (int mf = 0; mf < 4; mf++)
                LDSM4(a[mf][0], a[mf][1], a[mf][2], a[mf][3],
                      cur + (wm * 64 + mf * 16) * LD64 + kk * 32 + a_lrow);
            #pragma unroll
            for (int nfp = 0; nfp < 2; nfp++) {
                uint32_t b0, b1, b2, b3;
                LDSM4(b0, b1, b2, b3,
                      cur + XA2 + (wn * 32 + nfp * 16) * LD64 + kk * 32 + b_lrow);
                #pragma unroll
                for (int mf = 0; mf < 4; mf++) {
                    mma16816(acc[mf][nfp*2],   a[mf][0], a[mf][1], a[mf][2], a[mf][3], b0, b1);
                    mma16816(acc[mf][nfp*2+1], a[mf][0], a[mf][1], a[mf][2], a[mf][3], b2, b3);
                }
            }
        }
    }

    #pragma unroll
    for (int mf = 0; mf < 4; mf++) {
        #pragma unroll
        for (int half = 0; half < 2; half++) {
            const int m = m0 + wm * 64 + mf * 16 + (lane >> 2) + half * 8;
            const size_t ob = ((size_t)(m & 63) * Bdim + (m >> 6)) * H3;
            #pragma unroll
            for (int nf = 0; nf < 4; nf++) {
                const int jj = n0 + wn * 32 + nf * 8 + (lane & 3) * 2;
                const float ox = acc[mf][nf][half*2+0] + bih[jj];
                const float oy = acc[mf][nf][half*2+1] + bih[jj+1];
                *(__half2*)(g_xg16 + ob + jj) = __floats2half2_rn(ox, oy);
            }
        }
    }
}

// ---------------------------------------------------------------------------
// Persistent GRU: Whh resident; register-carried h; per-b-tile 8-CTA barriers.
// Warp tile m32 x (3 gates x 16 j): smem reads 896KB -> 640KB per step.
// ---------------------------------------------------------------------------
#define WB_SZ (192*WLD)            // 199680
#define GAST (64*LD64)             // 9216/stage, 3 stages
#define GRU_SMEM (WB_SZ + 3*GAST)  // 227328

__device__ __forceinline__ void gru_ldA(uint32_t dst, int tid, int b0, int c,
                                        const __half* __restrict__ h16){
    const int k0 = c * 64;
    #pragma unroll
    for (int i = 0; i < 2; i++) {            // 512 u4
        const int q = tid + i * 256;
        const int r = q >> 3, u = q & 7;
        CP16(dst + r * LD64 + u * 16, h16 + (size_t)(b0 + r) * Hdim + k0 + u * 8);
    }
}

__global__ __launch_bounds__(256, 1) void gru_pers(
    const float* __restrict__ bhh, float* __restrict__ outp)
{
    extern __shared__ __align__(16) char smp[];
    const uint32_t sb = smem_u32(smp);
    const uint32_t WB = sb;
    const uint32_t AB = sb + WB_SZ;
    const int tid = threadIdx.x, lane = tid & 31, wid = tid >> 5;
    const int wm = wid >> 2, wn = wid & 3;          // m32 x (3 x 16 j)
    const int bt = blockIdx.x;
    const int b0 = bt * 64, j0 = blockIdx.y * 64;
    unsigned* const cnt = &g_grp_cnt[bt * 32];
    unsigned* const gen = &g_grp_gen[bt * 32];

    // resident Whh: 192 rows x 512 halves
    for (int q = tid; q < 12288; q += 256) {
        const int r = q >> 6, u = q & 63;
        const int g = r >> 6, jj = r & 63;
        uint4 v = *(const uint4*)(g_Whh16 + (size_t)((g << 9) + j0 + jj) * Hdim + u * 8);
        STS16(WB + r * WLD + u * 16, v);
    }
    __syncthreads();

    const uint32_t a_lrow = (lane & 15) * LD64 + (lane >> 4) * 16;
    const uint32_t b_lrowW = ((lane >> 4) * 8 + (lane & 7)) * WLD + ((lane >> 3) & 1) * 16;

    // fixed per-thread coordinates
    const int jjb = j0 + wn * 16 + (lane & 3) * 2;        // + nfp*8
    const int brow[4] = {                                  // mf*2 + half
        b0 + wm * 32 + (lane >> 2),
        b0 + wm * 32 + (lane >> 2) + 8,
        b0 + wm * 32 + 16 + (lane >> 2),
        b0 + wm * 32 + 16 + (lane >> 2) + 8
    };

    float2 bhh_r[3][2];
    #pragma unroll
    for (int g = 0; g < 3; g++)
        #pragma unroll
        for (int nfp = 0; nfp < 2; nfp++)
            bhh_r[g][nfp] = *(const float2*)(bhh + g * Hdim + jjb + nfp * 8);

    float hold[4][2][2];                                   // [brow][nfp][cc]
    #pragma unroll
    for (int r4 = 0; r4 < 4; r4++)
        #pragma unroll
        for (int nfp = 0; nfp < 2; nfp++) { hold[r4][nfp][0] = 0.0f; hold[r4][nfp][1] = 0.0f; }

    for (int s = 0; s < Sdim; s++) {
        const int par = s & 1;
        const __half* __restrict__ h16 = g_h16[par];

        float acc[2][3][2][4];                             // [mf][g][nfp][frag]
        #pragma unroll
        for (int mf = 0; mf < 2; mf++)
            #pragma unroll
            for (int g = 0; g < 3; g++)
                #pragma unroll
                for (int nfp = 0; nfp < 2; nfp++)
                    #pragma unroll
                    for (int d = 0; d < 4; d++) acc[mf][g][nfp][d] = 0.0f;

        gru_ldA(AB, tid, b0, 0, h16); CP_COMMIT();
        gru_ldA(AB + GAST, tid, b0, 1, h16); CP_COMMIT();

        // epilogue operands (independent of h) — hidden behind MMA
        float gate[4];
        #pragma unroll
        for (int r4 = 0; r4 < 4; r4++) gate[r4] = g_G[s * Bdim + brow[r4]];
        __half2 xgp[4][3][2];
        #pragma unroll
        for (int r4 = 0; r4 < 4; r4++) {
            const __half* xrow = g_xg16 + ((size_t)s * Bdim + brow[r4]) * H3;
            #pragma unroll
            for (int g = 0; g < 3; g++)
                #pragma unroll
                for (int nfp = 0; nfp < 2; nfp++)
                    xgp[r4][g][nfp] = *(const __half2*)(xrow + g * Hdim + jjb + nfp * 8);
        }

        for (int c = 0; c < 8; c++) {
            CP_WAIT1();
            __syncthreads();
            if (c + 2 < 8) gru_ldA(AB + ((c + 2) % 3) * GAST, tid, b0, c + 2, h16);
            CP_COMMIT();
            const uint32_t cur = AB + (c % 3) * GAST;
            const uint32_t koff = c * 128;
            #pragma unroll
            for (int kk = 0; kk < 4; kk++) {
                uint32_t a[2][4];
                #pragma unroll
                for (int mf = 0; mf < 2; mf++)
                    LDSM4(a[mf][0], a[mf][1], a[mf][2], a[mf][3],
                          cur + (wm * 32 + mf * 16) * LD64 + a_lrow + kk * 32);
                #pragma unroll
                for (int g = 0; g < 3; g++) {
                    uint32_t b0r, b1r, b2r, b3r;
                    LDSM4(b0r, b1r, b2r, b3r,
                          WB + (g * 64 + wn * 16) * WLD + koff + kk * 32 + b_lrowW);
                    #pragma unroll
                    for (int mf = 0; mf < 2; mf++) {
                        mma16816(acc[mf][g][0], a[mf][0], a[mf][1], a[mf][2], a[mf][3], b0r, b1r);
                        mma16816(acc[mf][g][1], a[mf][0], a[mf][1], a[mf][2], a[mf][3], b2r, b3r);
                    }
                }
            }
        }

        const int last = (s == Sdim - 1);
        __half* __restrict__ h16N = g_h16[par ^ 1];

        #pragma unroll
        for (int mf = 0; mf < 2; mf++) {
            #pragma unroll
            for (int half = 0; half < 2; half++) {
                const int r4 = mf * 2 + half;
                const int bb = brow[r4];
                const float gt = gate[r4];
                #pragma unroll
                for (int nfp = 0; nfp < 2; nfp++) {
                    float hn2[2];
                    #pragma unroll
                    for (int cc = 0; cc < 2; cc++) {
                        const int ai = half * 2 + cc;
                        const float hr = acc[mf][0][nfp][ai] + (cc ? bhh_r[0][nfp].y : bhh_r[0][nfp].x);
                        const float hz = acc[mf][1][nfp][ai] + (cc ? bhh_r[1][nfp].y : bhh_r[1][nfp].x);
                        const float hnv = acc[mf][2][nfp][ai] + (cc ? bhh_r[2][nfp].y : bhh_r[2][nfp].x);
                        const float xr = cc ? __high2float(xgp[r4][0][nfp]) : __low2float(xgp[r4][0][nfp]);
                        const float xz = cc ? __high2float(xgp[r4][1][nfp]) : __low2float(xgp[r4][1][nfp]);
                        const float xn = cc ? __high2float(xgp[r4][2][nfp]) : __low2float(xgp[r4][2][nfp]);
                        const float r = sigmoidf_(xr + hr);
                        const float z = sigmoidf_(xz + hz);
                        const float n = tanhf_(xn + r * hnv);
                        const float ho = hold[r4][nfp][cc];
                        const float hnew = gt * ((1.0f - z) * n + z * ho) + (1.0f - gt) * ho;
                        hold[r4][nfp][cc] = hnew;
                        hn2[cc] = hnew;
                    }
                    if (last) {
                        *(float2*)(outp + (size_t)bb * Hdim + jjb + nfp * 8) = make_float2(hn2[0], hn2[1]);
                    } else {
                        *(__half2*)(h16N + (size_t)bb * Hdim + jjb + nfp * 8) = __floats2half2_rn(hn2[0], hn2[1]);
                    }
                }
            }
        }

        if (!last) {
            __syncthreads();
            if (tid == 0) {
                __threadfence();
                const unsigned target = (unsigned)(s + 1);
                unsigned arr = atomicAdd(cnt, 1u);
                if (arr == 7u) {
                    *cnt = 0u;
                    __threadfence();
                    atomicExch(gen, target);
                } else {
                    unsigned v;
                    do {
                        asm volatile("ld.acquire.gpu.u32 %0, [%1];" : "=r"(v) : "l"(gen));
                    } while (v < target);
                }
            }
            __syncthreads();
        }
    }
}

// ---------------------------------------------------------------------------
extern "C" void kernel_launch(void* const* d_in, const int* in_sizes, int n_in,
                              void* d_out, int out_size)
{
    const float* C    = (const float*)d_in[0];
    const float* Q    = (const float*)d_in[1];
    const float* PM   = (const float*)d_in[2];
    const float* fc1w = (const float*)d_in[3];
    const float* fc1b = (const float*)d_in[4];
    const float* fc2w = (const float*)d_in[5];
    const float* fc2b = (const float*)d_in[6];
    const float* Wih  = (const float*)d_in[7];
    const float* Whh  = (const float*)d_in[8];
    const float* bih  = (const float*)d_in[9];
    const float* bhh  = (const float*)d_in[10];
    float* out = (float*)d_out;

    static int configured = 0;
    if (!configured) {
        cudaFuncSetAttribute(G_mma,    cudaFuncAttributeMaxDynamicSharedMemorySize, 2 * GST3);
        cudaFuncSetAttribute(xg_mma,   cudaFuncAttributeMaxDynamicSharedMemorySize, 4 * XST);
        cudaFuncSetAttribute(gru_pers, cudaFuncAttributeMaxDynamicSharedMemorySize, GRU_SMEM);
        configured = 1;
    }

    zero_init_kernel<<<(Bdim*Hdim + 255)/256, 256>>>();
    cvt_C16_kernel<<<32768, 256>>>(C);
    cvt_W16_kernel<<<1792, 256>>>(Wih, Whh, fc1w);
    G_mma<<<Mrows/128, 256, 2 * GST3>>>(Q, PM, fc1b, fc2w, fc2b);
    xg_mma<<<dim3(Mrows/128, H3/256), 512, 4 * XST>>>(bih);
    gru_pers<<<dim3(Bdim/64, Hdim/64), 256, GRU_SMEM>>>(bhh, out);
}